// round 12
// baseline (speedup 1.0000x reference)
#include <cuda_runtime.h>
#include <math.h>

#define BB 1024
#define TT 200
#define EE 64
#define UU 64
#define HH 4
#define DH 16
#define C3U 192

typedef unsigned long long ull;
typedef unsigned int u32;
typedef unsigned short u16;

__device__ __align__(16) u16 g_wq[192 * 72];   // W^T bf16, rows padded to 72
__device__ __align__(16) u16 g_wo[64 * 72];    // Wo^T bf16

// ---------------------------------------------------------------------------
__device__ __forceinline__ u16 f2bf(float f) {
    u32 u = __float_as_uint(f);
    u32 r = u + 0x7FFFu + ((u >> 16) & 1u);
    return (u16)(r >> 16);
}
__device__ __forceinline__ u32 bfx2(float lo, float hi) {
    u32 r; asm("cvt.rn.bf16x2.f32 %0, %1, %2;" : "=r"(r) : "f"(hi), "f"(lo));
    return r;
}
__device__ __forceinline__ ull pack2(float x, float y) {
    ull r; asm("mov.b64 %0, {%1, %2};" : "=l"(r) : "f"(x), "f"(y)); return r;
}
__device__ __forceinline__ void unpack2(ull v, float& x, float& y) {
    asm("mov.b64 {%0, %1}, %2;" : "=f"(x), "=f"(y) : "l"(v));
}
__device__ __forceinline__ ull ffma2(ull a, ull b, ull c) {
    ull d; asm("fma.rn.f32x2 %0, %1, %2, %3;" : "=l"(d) : "l"(a), "l"(b), "l"(c)); return d;
}
__device__ __forceinline__ ull fmul2(ull a, ull b) {
    ull d; asm("mul.rn.f32x2 %0, %1, %2;" : "=l"(d) : "l"(a), "l"(b)); return d;
}
__device__ __forceinline__ ull fadd2(ull a, ull b) {
    ull d; asm("add.rn.f32x2 %0, %1, %2;" : "=l"(d) : "l"(a), "l"(b)); return d;
}

// packed 2^y (y already log2-scaled)
__device__ __forceinline__ ull exp2p(ull y2) {
    const float BIG = 12582912.0f;
    ull t2  = fadd2(y2, pack2(BIG, BIG));
    ull nf2 = fadd2(t2, pack2(-BIG, -BIG));
    ull r2  = ffma2(nf2, pack2(-1.f, -1.f), y2);
    ull p2  = ffma2(pack2(0.00133335581f, 0.00133335581f), r2,
                    pack2(0.00961812911f, 0.00961812911f));
    p2 = ffma2(p2, r2, pack2(0.0555041087f, 0.0555041087f));
    p2 = ffma2(p2, r2, pack2(0.240226507f, 0.240226507f));
    p2 = ffma2(p2, r2, pack2(0.693147182f, 0.693147182f));
    p2 = ffma2(p2, r2, pack2(1.f, 1.f));
    float pa, pb, ta, tb;
    unpack2(p2, pa, pb);
    unpack2(t2, ta, tb);
    const float e0 = __int_as_float(__float_as_int(pa) + (__float_as_int(ta) << 23));
    const float e1 = __int_as_float(__float_as_int(pb) + (__float_as_int(tb) << 23));
    return pack2(e0, e1);
}
__device__ __forceinline__ u32 cvt_bf16x2p(ull e2) {
    float x, y; unpack2(e2, x, y);
    return bfx2(x, y);
}

// ---------------------------------------------------------------------------
__device__ __forceinline__ u32 smem_u32(const void* p) {
    u32 a; asm("{ .reg .u64 t; cvta.to.shared.u64 t, %1; cvt.u32.u64 %0, t; }"
               : "=r"(a) : "l"(p));
    return a;
}
__device__ __forceinline__ void ldmx4(u32& r0, u32& r1, u32& r2, u32& r3, u32 a) {
    asm volatile("ldmatrix.sync.aligned.m8n8.x4.shared.b16 {%0,%1,%2,%3}, [%4];"
                 : "=r"(r0), "=r"(r1), "=r"(r2), "=r"(r3) : "r"(a));
}
__device__ __forceinline__ void ldmx4t(u32& r0, u32& r1, u32& r2, u32& r3, u32 a) {
    asm volatile("ldmatrix.sync.aligned.m8n8.x4.trans.shared.b16 {%0,%1,%2,%3}, [%4];"
                 : "=r"(r0), "=r"(r1), "=r"(r2), "=r"(r3) : "r"(a));
}
__device__ __forceinline__ void mma16816(float* c, const u32* a, u32 b0, u32 b1) {
    asm volatile(
        "mma.sync.aligned.m16n8k16.row.col.f32.bf16.bf16.f32 "
        "{%0,%1,%2,%3}, {%4,%5,%6,%7}, {%8,%9}, {%0,%1,%2,%3};"
        : "+f"(c[0]), "+f"(c[1]), "+f"(c[2]), "+f"(c[3])
        : "r"(a[0]), "r"(a[1]), "r"(a[2]), "r"(a[3]), "r"(b0), "r"(b1));
}
__device__ __forceinline__ void cp_async16(u32 dst, const void* src) {
    asm volatile("cp.async.cg.shared.global [%0], [%1], 16;" :: "r"(dst), "l"(src));
}

// ---------------------------------------------------------------------------
// Kernel 0: transpose + bf16 round of W and Wo (B operands, n-major).
// ---------------------------------------------------------------------------
__global__ void prep_weights(const float* __restrict__ W, const float* __restrict__ Wo)
{
    const int i = blockIdx.x * 256 + threadIdx.x;   // 0..16383
    if (i < 12288) {
        const int k = i / 192, n = i % 192;
        g_wq[n * 72 + k] = f2bf(W[i]);
    } else {
        const int j = i - 12288;
        const int k = j / 64, n = j % 64;
        g_wo[n * 72 + k] = f2bf(Wo[j]);
    }
}

// ---------------------------------------------------------------------------
// Fused kernel: one CTA per batch. 512 threads (16 warps).
// Phase 1: QKV = X@W, 52 (mtile,nc) tasks over 16 warps; K/V tasks for
//          row-tiles beyond kcnt are skipped (never read by phase 2).
// Phase 2: FA2 attention, K/V ldmatrix double-buffered.
// Phase 3: Y = O@Wo + X ; in-register LN -> out.
//
// smem map (bytes):
//   [0,      29952)  X bf16 [208][72] stride 144  -> reused as O after ph.1
//   [29952,  57600)  W^T bf16 [192][72] stride 144
//   [57600,  66816)  Wo^T bf16 [64][72] stride 144
//   [66816, 150016)  QKV bf16 [208][200] stride 400 (Q:0-63 K:64-127 V:128-191)
// ---------------------------------------------------------------------------
#define FU_X   0
#define FU_W   29952
#define FU_WO  57600
#define FU_QKV 66816
#define FU_SMEM 150016

__global__ __launch_bounds__(512, 1)
void fused_mha(const float* __restrict__ X, const int* __restrict__ lens,
               const float* __restrict__ gamma, const float* __restrict__ beta,
               float* __restrict__ out)
{
    extern __shared__ char sm[];
    const u32 sb = smem_u32(sm);
    const int tid = threadIdx.x;
    const int b = blockIdx.x;
    const size_t rowg0 = (size_t)b * TT;

    // ---- staging ----
    {   // cp.async W (1728 chunks) + Wo (576 chunks)
        const char* srcw = (const char*)g_wq;
        for (int i = tid; i < 1728; i += 512)
            cp_async16(sb + FU_W + i * 16, srcw + i * 16);
        const char* srco = (const char*)g_wo;
        for (int i = tid; i < 576; i += 512)
            cp_async16(sb + FU_WO + i * 16, srco + i * 16);
        asm volatile("cp.async.commit_group;");
    }
    {   // X fp32 -> bf16 [208][72]
        const float4* xs = (const float4*)(X + rowg0 * EE);
        for (int i = tid; i < 3200; i += 512) {
            float4 v = xs[i];
            const int r = i >> 4, q = i & 15;
            uint2 p;
            p.x = bfx2(v.x, v.y);
            p.y = bfx2(v.z, v.w);
            *(uint2*)(sm + FU_X + r * 144 + q * 8) = p;
        }
        if (tid < 72)   // zero pad rows 200..207
            *(uint4*)(sm + FU_X + 200 * 144 + tid * 16) = make_uint4(0, 0, 0, 0);
    }
    asm volatile("cp.async.wait_group 0;");
    __syncthreads();

    const int lane = tid & 31;
    const int w    = tid >> 5;      // 0..15
    const int grp  = lane >> 3;
    const int qd   = lane & 3;

    int len = lens[b];
    if (len < 1) len = 1;
    if (len > TT) len = TT;
    const int kcnt = (len + 15) >> 4;
    const float CSC = 0.36067376022224085f;   // 0.25 * log2(e)

    // ================= Phase 1: QKV GEMM (52 tasks over 16 warps) ===========
    {
        const u32 a_off = (u32)(((grp & 1) * 8 + (lane & 7)) * 144 + (grp >> 1) * 16);
        const u32 b_base = sb + FU_W +
            (u32)(((grp >> 1) * 8 + (lane & 7)) * 144 + (grp & 1) * 16);

        for (int t = w; t < 52; t += 16) {
            const int mm = t % 13;        // row tile
            const int nc = t / 13;        // 48-col chunk
            // chunks nc>=2 are pure K/V (cols 96-191); rows >= kcnt*16 unread
            if (nc >= 2 && mm >= kcnt) continue;

            const u32 a_base = sb + FU_X + (u32)(mm * 16) * 144 + a_off;
            float acc[6][4];
            #pragma unroll
            for (int j = 0; j < 6; j++)
                #pragma unroll
                for (int q = 0; q < 4; q++) acc[j][q] = 0.f;

            #pragma unroll
            for (int ks = 0; ks < 4; ks++) {
                const u32 kb = (u32)(ks * 32);
                u32 A[4];
                ldmx4(A[0], A[1], A[2], A[3], a_base + kb);
                #pragma unroll
                for (int jp = 0; jp < 3; jp++) {
                    u32 Bh[4];
                    ldmx4(Bh[0], Bh[1], Bh[2], Bh[3],
                          b_base + (u32)(nc * 6912 + jp * 2304) + kb);
                    mma16816(acc[jp * 2],     A, Bh[0], Bh[1]);
                    mma16816(acc[jp * 2 + 1], A, Bh[2], Bh[3]);
                }
            }
            const int rA = mm * 16 + (lane >> 2);
            const int rB = rA + 8;
            #pragma unroll
            for (int j = 0; j < 6; j++) {
                const int c = nc * 48 + 8 * j + 2 * qd;
                const float sc = (c < UU) ? CSC : 1.0f;
                *(u32*)(sm + FU_QKV + rA * 400 + c * 2) =
                    bfx2(acc[j][0] * sc, acc[j][1] * sc);
                *(u32*)(sm + FU_QKV + rB * 400 + c * 2) =
                    bfx2(acc[j][2] * sc, acc[j][3] * sc);
            }
        }
    }
    __syncthreads();

    // ================= Phase 2: attention (K/V ldmatrix double-buffered) ====
    {
        const u32 arow = (u32)(((grp & 1) * 8 + (lane & 7)) * 400 + (grp >> 1) * 16);
        const u32 krow = (u32)(((grp >> 1) * 8 + (lane & 7)) * 400 + (grp & 1) * 16);
        const u32 vrow = (u32)(((grp & 1) * 8 + (lane & 7)) * 400 + (grp >> 1) * 16);

        for (int t = w; t < 52; t += 16) {
            const int hh = t / 13;
            const int mm = t - hh * 13;
            const u32 hb = (u32)(hh * 32);

            u32 A[4];
            ldmx4(A[0], A[1], A[2], A[3],
                  sb + FU_QKV + (u32)(mm * 16) * 400 + hb + arow);
            const u32 ka = sb + FU_QKV + 128 + hb + krow;
            const u32 va = sb + FU_QKV + 256 + hb + vrow;

            float o0[4] = {0,0,0,0}, o1[4] = {0,0,0,0};
            ull lA = 0, lB = 0;

            u32 KB[4], VB[4];
            ldmx4(KB[0], KB[1], KB[2], KB[3], ka);
            ldmx4t(VB[0], VB[1], VB[2], VB[3], va);

            for (int np = 0; np < kcnt; np++) {
                u32 KN[4], VN[4];
                if (np + 1 < kcnt) {   // prefetch next chunk (warp-uniform)
                    ldmx4(KN[0], KN[1], KN[2], KN[3], ka + (u32)((np + 1) * 6400));
                    ldmx4t(VN[0], VN[1], VN[2], VN[3], va + (u32)((np + 1) * 6400));
                }

                const int c0 = np * 16 + 2 * qd;
                const ull m0 = pack2(c0 < len ? 1.f : 0.f, (c0 + 1) < len ? 1.f : 0.f);
                const ull m1 = pack2((c0 + 8) < len ? 1.f : 0.f, (c0 + 9) < len ? 1.f : 0.f);

                u32 aE[4];
                #pragma unroll
                for (int sub = 0; sub < 2; sub++) {
                    float s[4] = {0.f, 0.f, 0.f, 0.f};
                    mma16816(s, A, KB[sub * 2], KB[sub * 2 + 1]);
                    const ull m = sub ? m1 : m0;
                    const ull eA = fmul2(exp2p(pack2(s[0], s[1])), m);
                    const ull eB = fmul2(exp2p(pack2(s[2], s[3])), m);
                    lA = fadd2(lA, eA);
                    lB = fadd2(lB, eB);
                    aE[sub * 2]     = cvt_bf16x2p(eA);
                    aE[sub * 2 + 1] = cvt_bf16x2p(eB);
                }
                mma16816(o0, aE, VB[0], VB[1]);
                mma16816(o1, aE, VB[2], VB[3]);

                #pragma unroll
                for (int r = 0; r < 4; r++) { KB[r] = KN[r]; VB[r] = VN[r]; }
            }

            // normalize + store O (bf16) into the retired X buffer
            float x, y;
            unpack2(lA, x, y); float la = x + y;
            la += __shfl_xor_sync(0xFFFFFFFFu, la, 1);
            la += __shfl_xor_sync(0xFFFFFFFFu, la, 2);
            unpack2(lB, x, y); float lb = x + y;
            lb += __shfl_xor_sync(0xFFFFFFFFu, lb, 1);
            lb += __shfl_xor_sync(0xFFFFFFFFu, lb, 2);
            const float iA = 1.f / la, iB = 1.f / lb;
            const int cb = hh * 16 + 2 * qd;
            const int rA = mm * 16 + (lane >> 2), rB = rA + 8;
            if (rA < TT) {
                *(u32*)(sm + FU_X + rA * 144 + cb * 2)      = bfx2(o0[0] * iA, o0[1] * iA);
                *(u32*)(sm + FU_X + rA * 144 + cb * 2 + 16) = bfx2(o1[0] * iA, o1[1] * iA);
            }
            if (rB < TT) {
                *(u32*)(sm + FU_X + rB * 144 + cb * 2)      = bfx2(o0[2] * iB, o0[3] * iB);
                *(u32*)(sm + FU_X + rB * 144 + cb * 2 + 16) = bfx2(o1[2] * iB, o1[3] * iB);
            }
        }
    }
    __syncthreads();

    // ================= Phase 3: projection + residual + LN =================
    if (w < 13) {
        const u32 a_base = sb + FU_X +
            (u32)((w * 16 + (grp & 1) * 8 + (lane & 7)) * 144 + (grp >> 1) * 16);
        const u32 b_base = sb + FU_WO +
            (u32)(((grp >> 1) * 8 + (lane & 7)) * 144 + (grp & 1) * 16);

        float acc[8][4];
        #pragma unroll
        for (int j = 0; j < 8; j++)
            #pragma unroll
            for (int q = 0; q < 4; q++) acc[j][q] = 0.f;

        #pragma unroll
        for (int ks = 0; ks < 4; ks++) {
            const u32 kb = (u32)(ks * 32);
            u32 Af[4];
            ldmx4(Af[0], Af[1], Af[2], Af[3], a_base + kb);
            #pragma unroll
            for (int jp = 0; jp < 4; jp++) {
                u32 Bh[4];
                ldmx4(Bh[0], Bh[1], Bh[2], Bh[3], b_base + (u32)(jp * 2304) + kb);
                mma16816(acc[jp * 2],     Af, Bh[0], Bh[1]);
                mma16816(acc[jp * 2 + 1], Af, Bh[2], Bh[3]);
            }
        }

        const int rAl = w * 16 + (lane >> 2);
        const int rBl = rAl + 8;
        const bool okB = rBl < TT;
        const size_t rowA = rowg0 + rAl;
        const size_t rowB = rowg0 + rBl;
        const int cq = 2 * qd;

        #pragma unroll
        for (int j = 0; j < 8; j++) {
            const int c = 8 * j + cq;
            float2 xa = *(const float2*)(X + rowA * UU + c);
            acc[j][0] += xa.x; acc[j][1] += xa.y;
            if (okB) {
                float2 xb = *(const float2*)(X + rowB * UU + c);
                acc[j][2] += xb.x; acc[j][3] += xb.y;
            }
        }

        float sA = 0.f, sB = 0.f;
        #pragma unroll
        for (int j = 0; j < 8; j++) {
            sA += acc[j][0] + acc[j][1];
            sB += acc[j][2] + acc[j][3];
        }
        sA += __shfl_xor_sync(0xFFFFFFFFu, sA, 1);
        sA += __shfl_xor_sync(0xFFFFFFFFu, sA, 2);
        sB += __shfl_xor_sync(0xFFFFFFFFu, sB, 1);
        sB += __shfl_xor_sync(0xFFFFFFFFu, sB, 2);
        const float mA = sA * (1.0f / 64.0f);
        const float mB = sB * (1.0f / 64.0f);

        float vA = 0.f, vB = 0.f;
        #pragma unroll
        for (int j = 0; j < 8; j++) {
            float d0 = acc[j][0] - mA, d1 = acc[j][1] - mA;
            float d2 = acc[j][2] - mB, d3 = acc[j][3] - mB;
            vA = fmaf(d0, d0, fmaf(d1, d1, vA));
            vB = fmaf(d2, d2, fmaf(d3, d3, vB));
        }
        vA += __shfl_xor_sync(0xFFFFFFFFu, vA, 1);
        vA += __shfl_xor_sync(0xFFFFFFFFu, vA, 2);
        vB += __shfl_xor_sync(0xFFFFFFFFu, vB, 1);
        vB += __shfl_xor_sync(0xFFFFFFFFu, vB, 2);
        const float iA = rsqrtf(vA * (1.0f / 64.0f) + 1e-9f);
        const float iB = rsqrtf(vB * (1.0f / 64.0f) + 1e-9f);

        #pragma unroll
        for (int j = 0; j < 8; j++) {
            const int c = 8 * j + cq;
            const float2 gg = *(const float2*)(gamma + c);
            const float2 bb = *(const float2*)(beta + c);
            float2 oa;
            oa.x = fmaf((acc[j][0] - mA) * iA, gg.x, bb.x);
            oa.y = fmaf((acc[j][1] - mA) * iA, gg.y, bb.y);
            *(float2*)(out + rowA * UU + c) = oa;
            if (okB) {
                float2 ob;
                ob.x = fmaf((acc[j][2] - mB) * iB, gg.x, bb.x);
                ob.y = fmaf((acc[j][3] - mB) * iB, gg.y, bb.y);
                *(float2*)(out + rowB * UU + c) = ob;
            }
        }
    }
}

// ---------------------------------------------------------------------------
extern "C" void kernel_launch(void* const* d_in, const int* in_sizes, int n_in,
                              void* d_out, int out_size)
{
    const float* input_info = (const float*)d_in[0];
    const int*   keys_len   = (const int*)d_in[1];
    const float* W          = (const float*)d_in[2];
    const float* W_output   = (const float*)d_in[3];
    const float* gamma      = (const float*)d_in[4];
    const float* beta       = (const float*)d_in[5];
    float* out = (float*)d_out;

    cudaFuncSetAttribute(fused_mha, cudaFuncAttributeMaxDynamicSharedMemorySize, FU_SMEM);

    prep_weights<<<64, 256>>>(W, W_output);
    fused_mha<<<BB, 512, FU_SMEM>>>(input_info, keys_len, gamma, beta, out);
}

// round 13
// speedup vs baseline: 1.0143x; 1.0143x over previous
#include <cuda_runtime.h>
#include <math.h>

#define BB 1024
#define TT 200
#define EE 64
#define UU 64
#define HH 4
#define DH 16
#define C3U 192

typedef unsigned long long ull;
typedef unsigned int u32;
typedef unsigned short u16;

__device__ __align__(16) u16 g_wq[192 * 72];   // W^T bf16, rows padded to 72
__device__ __align__(16) u16 g_wo[64 * 72];    // Wo^T bf16

// ---------------------------------------------------------------------------
__device__ __forceinline__ u16 f2bf(float f) {
    u32 u = __float_as_uint(f);
    u32 r = u + 0x7FFFu + ((u >> 16) & 1u);
    return (u16)(r >> 16);
}
__device__ __forceinline__ u32 bfx2(float lo, float hi) {
    u32 r; asm("cvt.rn.bf16x2.f32 %0, %1, %2;" : "=r"(r) : "f"(hi), "f"(lo));
    return r;
}
__device__ __forceinline__ ull pack2(float x, float y) {
    ull r; asm("mov.b64 %0, {%1, %2};" : "=l"(r) : "f"(x), "f"(y)); return r;
}
__device__ __forceinline__ void unpack2(ull v, float& x, float& y) {
    asm("mov.b64 {%0, %1}, %2;" : "=f"(x), "=f"(y) : "l"(v));
}
__device__ __forceinline__ ull ffma2(ull a, ull b, ull c) {
    ull d; asm("fma.rn.f32x2 %0, %1, %2, %3;" : "=l"(d) : "l"(a), "l"(b), "l"(c)); return d;
}
__device__ __forceinline__ ull fmul2(ull a, ull b) {
    ull d; asm("mul.rn.f32x2 %0, %1, %2;" : "=l"(d) : "l"(a), "l"(b)); return d;
}
__device__ __forceinline__ ull fadd2(ull a, ull b) {
    ull d; asm("add.rn.f32x2 %0, %1, %2;" : "=l"(d) : "l"(a), "l"(b)); return d;
}

// packed 2^y (y already log2-scaled)
__device__ __forceinline__ ull exp2p(ull y2) {
    const float BIG = 12582912.0f;
    ull t2  = fadd2(y2, pack2(BIG, BIG));
    ull nf2 = fadd2(t2, pack2(-BIG, -BIG));
    ull r2  = ffma2(nf2, pack2(-1.f, -1.f), y2);
    ull p2  = ffma2(pack2(0.00133335581f, 0.00133335581f), r2,
                    pack2(0.00961812911f, 0.00961812911f));
    p2 = ffma2(p2, r2, pack2(0.0555041087f, 0.0555041087f));
    p2 = ffma2(p2, r2, pack2(0.240226507f, 0.240226507f));
    p2 = ffma2(p2, r2, pack2(0.693147182f, 0.693147182f));
    p2 = ffma2(p2, r2, pack2(1.f, 1.f));
    float pa, pb, ta, tb;
    unpack2(p2, pa, pb);
    unpack2(t2, ta, tb);
    const float e0 = __int_as_float(__float_as_int(pa) + (__float_as_int(ta) << 23));
    const float e1 = __int_as_float(__float_as_int(pb) + (__float_as_int(tb) << 23));
    return pack2(e0, e1);
}
__device__ __forceinline__ u32 cvt_bf16x2p(ull e2) {
    float x, y; unpack2(e2, x, y);
    return bfx2(x, y);
}

// ---------------------------------------------------------------------------
__device__ __forceinline__ u32 smem_u32(const void* p) {
    u32 a; asm("{ .reg .u64 t; cvta.to.shared.u64 t, %1; cvt.u32.u64 %0, t; }"
               : "=r"(a) : "l"(p));
    return a;
}
__device__ __forceinline__ void ldmx4(u32& r0, u32& r1, u32& r2, u32& r3, u32 a) {
    asm volatile("ldmatrix.sync.aligned.m8n8.x4.shared.b16 {%0,%1,%2,%3}, [%4];"
                 : "=r"(r0), "=r"(r1), "=r"(r2), "=r"(r3) : "r"(a));
}
__device__ __forceinline__ void ldmx4t(u32& r0, u32& r1, u32& r2, u32& r3, u32 a) {
    asm volatile("ldmatrix.sync.aligned.m8n8.x4.trans.shared.b16 {%0,%1,%2,%3}, [%4];"
                 : "=r"(r0), "=r"(r1), "=r"(r2), "=r"(r3) : "r"(a));
}
__device__ __forceinline__ void mma16816(float* c, const u32* a, u32 b0, u32 b1) {
    asm volatile(
        "mma.sync.aligned.m16n8k16.row.col.f32.bf16.bf16.f32 "
        "{%0,%1,%2,%3}, {%4,%5,%6,%7}, {%8,%9}, {%0,%1,%2,%3};"
        : "+f"(c[0]), "+f"(c[1]), "+f"(c[2]), "+f"(c[3])
        : "r"(a[0]), "r"(a[1]), "r"(a[2]), "r"(a[3]), "r"(b0), "r"(b1));
}
__device__ __forceinline__ void cp_async16(u32 dst, const void* src) {
    asm volatile("cp.async.cg.shared.global [%0], [%1], 16;" :: "r"(dst), "l"(src));
}

// ---------------------------------------------------------------------------
// Kernel 0: transpose + bf16 round of W and Wo (B operands, n-major).
// ---------------------------------------------------------------------------
__global__ void prep_weights(const float* __restrict__ W, const float* __restrict__ Wo)
{
    const int i = blockIdx.x * 256 + threadIdx.x;   // 0..16383
    if (i < 12288) {
        const int k = i / 192, n = i % 192;
        g_wq[n * 72 + k] = f2bf(W[i]);
    } else {
        const int j = i - 12288;
        const int k = j / 64, n = j % 64;
        g_wo[n * 72 + k] = f2bf(Wo[j]);
    }
}

// ---------------------------------------------------------------------------
// Fused kernel: one CTA per batch. 512 threads (16 warps).
// Phase 1: QKV = X@W (tasks over 16 warps, masked-length skip for K/V cols)
// Phase 2: FA2 attention, 28 (head, mtile-PAIR) tasks: K/V loaded once per
//          chunk, two independent S->exp->O chains (2-way ILP on the path).
// Phase 3: Y = O@Wo + X ; in-register LN -> out.
//
// smem map (bytes):
//   [0,      29952)  X bf16 [208][72] stride 144  -> reused as O after ph.1
//   [29952,  57600)  W^T bf16 [192][72] stride 144
//   [57600,  66816)  Wo^T bf16 [64][72] stride 144
//   [66816, 150016)  QKV bf16 [208][200] stride 400 (Q:0-63 K:64-127 V:128-191)
// ---------------------------------------------------------------------------
#define FU_X   0
#define FU_W   29952
#define FU_WO  57600
#define FU_QKV 66816
#define FU_SMEM 150016

__global__ __launch_bounds__(512, 1)
void fused_mha(const float* __restrict__ X, const int* __restrict__ lens,
               const float* __restrict__ gamma, const float* __restrict__ beta,
               float* __restrict__ out)
{
    extern __shared__ char sm[];
    const u32 sb = smem_u32(sm);
    const int tid = threadIdx.x;
    const int b = blockIdx.x;
    const size_t rowg0 = (size_t)b * TT;

    // ---- staging ----
    {   // cp.async W (1728 chunks) + Wo (576 chunks)
        const char* srcw = (const char*)g_wq;
        for (int i = tid; i < 1728; i += 512)
            cp_async16(sb + FU_W + i * 16, srcw + i * 16);
        const char* srco = (const char*)g_wo;
        for (int i = tid; i < 576; i += 512)
            cp_async16(sb + FU_WO + i * 16, srco + i * 16);
        asm volatile("cp.async.commit_group;");
    }
    {   // X fp32 -> bf16 [208][72]
        const float4* xs = (const float4*)(X + rowg0 * EE);
        for (int i = tid; i < 3200; i += 512) {
            float4 v = xs[i];
            const int r = i >> 4, q = i & 15;
            uint2 p;
            p.x = bfx2(v.x, v.y);
            p.y = bfx2(v.z, v.w);
            *(uint2*)(sm + FU_X + r * 144 + q * 8) = p;
        }
        if (tid < 72)   // zero pad rows 200..207
            *(uint4*)(sm + FU_X + 200 * 144 + tid * 16) = make_uint4(0, 0, 0, 0);
    }
    asm volatile("cp.async.wait_group 0;");
    __syncthreads();

    const int lane = tid & 31;
    const int w    = tid >> 5;      // 0..15
    const int grp  = lane >> 3;
    const int qd   = lane & 3;

    int len = lens[b];
    if (len < 1) len = 1;
    if (len > TT) len = TT;
    const int kcnt = (len + 15) >> 4;
    const float CSC = 0.36067376022224085f;   // 0.25 * log2(e)

    // ================= Phase 1: QKV GEMM (52 tasks over 16 warps) ===========
    {
        const u32 a_off = (u32)(((grp & 1) * 8 + (lane & 7)) * 144 + (grp >> 1) * 16);
        const u32 b_base = sb + FU_W +
            (u32)(((grp >> 1) * 8 + (lane & 7)) * 144 + (grp & 1) * 16);

        for (int t = w; t < 52; t += 16) {
            const int mm = t % 13;        // row tile
            const int nc = t / 13;        // 48-col chunk
            if (nc >= 2 && mm >= kcnt) continue;   // K/V rows never read

            const u32 a_base = sb + FU_X + (u32)(mm * 16) * 144 + a_off;
            float acc[6][4];
            #pragma unroll
            for (int j = 0; j < 6; j++)
                #pragma unroll
                for (int q = 0; q < 4; q++) acc[j][q] = 0.f;

            #pragma unroll
            for (int ks = 0; ks < 4; ks++) {
                const u32 kb = (u32)(ks * 32);
                u32 A[4];
                ldmx4(A[0], A[1], A[2], A[3], a_base + kb);
                #pragma unroll
                for (int jp = 0; jp < 3; jp++) {
                    u32 Bh[4];
                    ldmx4(Bh[0], Bh[1], Bh[2], Bh[3],
                          b_base + (u32)(nc * 6912 + jp * 2304) + kb);
                    mma16816(acc[jp * 2],     A, Bh[0], Bh[1]);
                    mma16816(acc[jp * 2 + 1], A, Bh[2], Bh[3]);
                }
            }
            const int rA = mm * 16 + (lane >> 2);
            const int rB = rA + 8;
            #pragma unroll
            for (int j = 0; j < 6; j++) {
                const int c = nc * 48 + 8 * j + 2 * qd;
                const float sc = (c < UU) ? CSC : 1.0f;
                *(u32*)(sm + FU_QKV + rA * 400 + c * 2) =
                    bfx2(acc[j][0] * sc, acc[j][1] * sc);
                *(u32*)(sm + FU_QKV + rB * 400 + c * 2) =
                    bfx2(acc[j][2] * sc, acc[j][3] * sc);
            }
        }
    }
    __syncthreads();

    // ===== Phase 2: attention, 28 (head, mtile-pair) tasks, dual chains =====
    {
        const u32 arow = (u32)(((grp & 1) * 8 + (lane & 7)) * 400 + (grp >> 1) * 16);
        const u32 krow = (u32)(((grp >> 1) * 8 + (lane & 7)) * 400 + (grp & 1) * 16);
        const u32 vrow = (u32)(((grp & 1) * 8 + (lane & 7)) * 400 + (grp >> 1) * 16);

        for (int t = w; t < 28; t += 16) {
            const int hh = t / 7;
            const int mp = t - hh * 7;
            const int mt0 = 2 * mp, mt1 = 2 * mp + 1;
            const bool do1 = (mt1 < 13);
            const u32 hb = (u32)(hh * 32);

            u32 A0[4], A1[4];
            const u32 a0 = sb + FU_QKV + (u32)(mt0 * 16) * 400 + hb + arow;
            ldmx4(A0[0], A0[1], A0[2], A0[3], a0);
            if (do1) {
                ldmx4(A1[0], A1[1], A1[2], A1[3], a0 + 6400);
            } else {
                A1[0] = A0[0]; A1[1] = A0[1]; A1[2] = A0[2]; A1[3] = A0[3];
            }
            const u32 ka = sb + FU_QKV + 128 + hb + krow;
            const u32 va = sb + FU_QKV + 256 + hb + vrow;

            float o00[4] = {0,0,0,0}, o01[4] = {0,0,0,0};
            float o10[4] = {0,0,0,0}, o11[4] = {0,0,0,0};
            ull lA0 = 0, lB0 = 0, lA1 = 0, lB1 = 0;

            for (int np = 0; np < kcnt; np++) {
                u32 KB[4], VB[4];
                ldmx4(KB[0], KB[1], KB[2], KB[3], ka + (u32)(np * 6400));
                ldmx4t(VB[0], VB[1], VB[2], VB[3], va + (u32)(np * 6400));

                const int c0 = np * 16 + 2 * qd;
                const ull m0 = pack2(c0 < len ? 1.f : 0.f, (c0 + 1) < len ? 1.f : 0.f);
                const ull m1 = pack2((c0 + 8) < len ? 1.f : 0.f, (c0 + 9) < len ? 1.f : 0.f);

                u32 aE0[4], aE1[4];
                #pragma unroll
                for (int sub = 0; sub < 2; sub++) {
                    float s0[4] = {0.f, 0.f, 0.f, 0.f};
                    float s1[4] = {0.f, 0.f, 0.f, 0.f};
                    mma16816(s0, A0, KB[sub * 2], KB[sub * 2 + 1]);
                    mma16816(s1, A1, KB[sub * 2], KB[sub * 2 + 1]);
                    const ull m = sub ? m1 : m0;
                    const ull eA0 = fmul2(exp2p(pack2(s0[0], s0[1])), m);
                    const ull eB0 = fmul2(exp2p(pack2(s0[2], s0[3])), m);
                    const ull eA1 = fmul2(exp2p(pack2(s1[0], s1[1])), m);
                    const ull eB1 = fmul2(exp2p(pack2(s1[2], s1[3])), m);
                    lA0 = fadd2(lA0, eA0);
                    lB0 = fadd2(lB0, eB0);
                    lA1 = fadd2(lA1, eA1);
                    lB1 = fadd2(lB1, eB1);
                    aE0[sub * 2]     = cvt_bf16x2p(eA0);
                    aE0[sub * 2 + 1] = cvt_bf16x2p(eB0);
                    aE1[sub * 2]     = cvt_bf16x2p(eA1);
                    aE1[sub * 2 + 1] = cvt_bf16x2p(eB1);
                }
                mma16816(o00, aE0, VB[0], VB[1]);
                mma16816(o01, aE0, VB[2], VB[3]);
                mma16816(o10, aE1, VB[0], VB[1]);
                mma16816(o11, aE1, VB[2], VB[3]);
            }

            // normalize + store O (bf16) into the retired X buffer
            const int cb = hh * 16 + 2 * qd;
            {
                float x, y;
                unpack2(lA0, x, y); float la = x + y;
                la += __shfl_xor_sync(0xFFFFFFFFu, la, 1);
                la += __shfl_xor_sync(0xFFFFFFFFu, la, 2);
                unpack2(lB0, x, y); float lb = x + y;
                lb += __shfl_xor_sync(0xFFFFFFFFu, lb, 1);
                lb += __shfl_xor_sync(0xFFFFFFFFu, lb, 2);
                const float iA = 1.f / la, iB = 1.f / lb;
                const int rA = mt0 * 16 + (lane >> 2), rB = rA + 8;
                if (rA < TT) {
                    *(u32*)(sm + FU_X + rA * 144 + cb * 2)      = bfx2(o00[0] * iA, o00[1] * iA);
                    *(u32*)(sm + FU_X + rA * 144 + cb * 2 + 16) = bfx2(o01[0] * iA, o01[1] * iA);
                }
                if (rB < TT) {
                    *(u32*)(sm + FU_X + rB * 144 + cb * 2)      = bfx2(o00[2] * iB, o00[3] * iB);
                    *(u32*)(sm + FU_X + rB * 144 + cb * 2 + 16) = bfx2(o01[2] * iB, o01[3] * iB);
                }
            }
            if (do1) {
                float x, y;
                unpack2(lA1, x, y); float la = x + y;
                la += __shfl_xor_sync(0xFFFFFFFFu, la, 1);
                la += __shfl_xor_sync(0xFFFFFFFFu, la, 2);
                unpack2(lB1, x, y); float lb = x + y;
                lb += __shfl_xor_sync(0xFFFFFFFFu, lb, 1);
                lb += __shfl_xor_sync(0xFFFFFFFFu, lb, 2);
                const float iA = 1.f / la, iB = 1.f / lb;
                const int rA = mt1 * 16 + (lane >> 2), rB = rA + 8;
                if (rA < TT) {
                    *(u32*)(sm + FU_X + rA * 144 + cb * 2)      = bfx2(o10[0] * iA, o10[1] * iA);
                    *(u32*)(sm + FU_X + rA * 144 + cb * 2 + 16) = bfx2(o11[0] * iA, o11[1] * iA);
                }
                if (rB < TT) {
                    *(u32*)(sm + FU_X + rB * 144 + cb * 2)      = bfx2(o10[2] * iB, o10[3] * iB);
                    *(u32*)(sm + FU_X + rB * 144 + cb * 2 + 16) = bfx2(o11[2] * iB, o11[3] * iB);
                }
            }
        }
    }
    __syncthreads();

    // ================= Phase 3: projection + residual + LN =================
    if (w < 13) {
        const u32 a_base = sb + FU_X +
            (u32)((w * 16 + (grp & 1) * 8 + (lane & 7)) * 144 + (grp >> 1) * 16);
        const u32 b_base = sb + FU_WO +
            (u32)(((grp >> 1) * 8 + (lane & 7)) * 144 + (grp & 1) * 16);

        float acc[8][4];
        #pragma unroll
        for (int j = 0; j < 8; j++)
            #pragma unroll
            for (int q = 0; q < 4; q++) acc[j][q] = 0.f;

        #pragma unroll
        for (int ks = 0; ks < 4; ks++) {
            const u32 kb = (u32)(ks * 32);
            u32 Af[4];
            ldmx4(Af[0], Af[1], Af[2], Af[3], a_base + kb);
            #pragma unroll
            for (int jp = 0; jp < 4; jp++) {
                u32 Bh[4];
                ldmx4(Bh[0], Bh[1], Bh[2], Bh[3], b_base + (u32)(jp * 2304) + kb);
                mma16816(acc[jp * 2],     Af, Bh[0], Bh[1]);
                mma16816(acc[jp * 2 + 1], Af, Bh[2], Bh[3]);
            }
        }

        const int rAl = w * 16 + (lane >> 2);
        const int rBl = rAl + 8;
        const bool okB = rBl < TT;
        const size_t rowA = rowg0 + rAl;
        const size_t rowB = rowg0 + rBl;
        const int cq = 2 * qd;

        #pragma unroll
        for (int j = 0; j < 8; j++) {
            const int c = 8 * j + cq;
            float2 xa = *(const float2*)(X + rowA * UU + c);
            acc[j][0] += xa.x; acc[j][1] += xa.y;
            if (okB) {
                float2 xb = *(const float2*)(X + rowB * UU + c);
                acc[j][2] += xb.x; acc[j][3] += xb.y;
            }
        }

        float sA = 0.f, sB = 0.f;
        #pragma unroll
        for (int j = 0; j < 8; j++) {
            sA += acc[j][0] + acc[j][1];
            sB += acc[j][2] + acc[j][3];
        }
        sA += __shfl_xor_sync(0xFFFFFFFFu, sA, 1);
        sA += __shfl_xor_sync(0xFFFFFFFFu, sA, 2);
        sB += __shfl_xor_sync(0xFFFFFFFFu, sB, 1);
        sB += __shfl_xor_sync(0xFFFFFFFFu, sB, 2);
        const float mA = sA * (1.0f / 64.0f);
        const float mB = sB * (1.0f / 64.0f);

        float vA = 0.f, vB = 0.f;
        #pragma unroll
        for (int j = 0; j < 8; j++) {
            float d0 = acc[j][0] - mA, d1 = acc[j][1] - mA;
            float d2 = acc[j][2] - mB, d3 = acc[j][3] - mB;
            vA = fmaf(d0, d0, fmaf(d1, d1, vA));
            vB = fmaf(d2, d2, fmaf(d3, d3, vB));
        }
        vA += __shfl_xor_sync(0xFFFFFFFFu, vA, 1);
        vA += __shfl_xor_sync(0xFFFFFFFFu, vA, 2);
        vB += __shfl_xor_sync(0xFFFFFFFFu, vB, 1);
        vB += __shfl_xor_sync(0xFFFFFFFFu, vB, 2);
        const float iA = rsqrtf(vA * (1.0f / 64.0f) + 1e-9f);
        const float iB = rsqrtf(vB * (1.0f / 64.0f) + 1e-9f);

        #pragma unroll
        for (int j = 0; j < 8; j++) {
            const int c = 8 * j + cq;
            const float2 gg = *(const float2*)(gamma + c);
            const float2 bb = *(const float2*)(beta + c);
            float2 oa;
            oa.x = fmaf((acc[j][0] - mA) * iA, gg.x, bb.x);
            oa.y = fmaf((acc[j][1] - mA) * iA, gg.y, bb.y);
            *(float2*)(out + rowA * UU + c) = oa;
            if (okB) {
                float2 ob;
                ob.x = fmaf((acc[j][2] - mB) * iB, gg.x, bb.x);
                ob.y = fmaf((acc[j][3] - mB) * iB, gg.y, bb.y);
                *(float2*)(out + rowB * UU + c) = ob;
            }
        }
    }
}

// ---------------------------------------------------------------------------
extern "C" void kernel_launch(void* const* d_in, const int* in_sizes, int n_in,
                              void* d_out, int out_size)
{
    const float* input_info = (const float*)d_in[0];
    const int*   keys_len   = (const int*)d_in[1];
    const float* W          = (const float*)d_in[2];
    const float* W_output   = (const float*)d_in[3];
    const float* gamma      = (const float*)d_in[4];
    const float* beta       = (const float*)d_in[5];
    float* out = (float*)d_out;

    cudaFuncSetAttribute(fused_mha, cudaFuncAttributeMaxDynamicSharedMemorySize, FU_SMEM);

    prep_weights<<<64, 256>>>(W, W_output);
    fused_mha<<<BB, 512, FU_SMEM>>>(input_info, keys_len, gamma, beta, out);
}

// round 14
// speedup vs baseline: 1.2251x; 1.2079x over previous
#include <cuda_runtime.h>
#include <math.h>

#define BB 1024
#define TT 200
#define EE 64
#define UU 64
#define HH 4
#define DH 16
#define C3U 192

typedef unsigned long long ull;
typedef unsigned int u32;
typedef unsigned short u16;

// Fragment-linearized weight tables (exact ldmatrix lane results).
// g_wqf: phase-1 W frags: [(nc*3+jp)*4+ks][4 regs][32 lanes] u32 -> 6144 u32
// g_wof: phase-3 Wo frags: [jp*4+ks][4 regs][32 lanes] u32        -> 2048 u32
__device__ __align__(16) u32 g_wqf[6144];
__device__ __align__(16) u32 g_wof[2048];

// ---------------------------------------------------------------------------
__device__ __forceinline__ u16 f2bf(float f) {
    u32 u = __float_as_uint(f);
    u32 r = u + 0x7FFFu + ((u >> 16) & 1u);
    return (u16)(r >> 16);
}
__device__ __forceinline__ u32 bfx2(float lo, float hi) {
    u32 r; asm("cvt.rn.bf16x2.f32 %0, %1, %2;" : "=r"(r) : "f"(hi), "f"(lo));
    return r;
}
__device__ __forceinline__ ull pack2(float x, float y) {
    ull r; asm("mov.b64 %0, {%1, %2};" : "=l"(r) : "f"(x), "f"(y)); return r;
}
__device__ __forceinline__ void unpack2(ull v, float& x, float& y) {
    asm("mov.b64 {%0, %1}, %2;" : "=f"(x), "=f"(y) : "l"(v));
}
__device__ __forceinline__ ull ffma2(ull a, ull b, ull c) {
    ull d; asm("fma.rn.f32x2 %0, %1, %2, %3;" : "=l"(d) : "l"(a), "l"(b), "l"(c)); return d;
}
__device__ __forceinline__ ull fmul2(ull a, ull b) {
    ull d; asm("mul.rn.f32x2 %0, %1, %2;" : "=l"(d) : "l"(a), "l"(b)); return d;
}
__device__ __forceinline__ ull fadd2(ull a, ull b) {
    ull d; asm("add.rn.f32x2 %0, %1, %2;" : "=l"(d) : "l"(a), "l"(b)); return d;
}

// packed 2^y (y already log2-scaled)
__device__ __forceinline__ ull exp2p(ull y2) {
    const float BIG = 12582912.0f;
    ull t2  = fadd2(y2, pack2(BIG, BIG));
    ull nf2 = fadd2(t2, pack2(-BIG, -BIG));
    ull r2  = ffma2(nf2, pack2(-1.f, -1.f), y2);
    ull p2  = ffma2(pack2(0.00133335581f, 0.00133335581f), r2,
                    pack2(0.00961812911f, 0.00961812911f));
    p2 = ffma2(p2, r2, pack2(0.0555041087f, 0.0555041087f));
    p2 = ffma2(p2, r2, pack2(0.240226507f, 0.240226507f));
    p2 = ffma2(p2, r2, pack2(0.693147182f, 0.693147182f));
    p2 = ffma2(p2, r2, pack2(1.f, 1.f));
    float pa, pb, ta, tb;
    unpack2(p2, pa, pb);
    unpack2(t2, ta, tb);
    const float e0 = __int_as_float(__float_as_int(pa) + (__float_as_int(ta) << 23));
    const float e1 = __int_as_float(__float_as_int(pb) + (__float_as_int(tb) << 23));
    return pack2(e0, e1);
}
__device__ __forceinline__ u32 cvt_bf16x2p(ull e2) {
    float x, y; unpack2(e2, x, y);
    return bfx2(x, y);
}

// ---------------------------------------------------------------------------
__device__ __forceinline__ u32 smem_u32(const void* p) {
    u32 a; asm("{ .reg .u64 t; cvta.to.shared.u64 t, %1; cvt.u32.u64 %0, t; }"
               : "=r"(a) : "l"(p));
    return a;
}
__device__ __forceinline__ void ldmx4(u32& r0, u32& r1, u32& r2, u32& r3, u32 a) {
    asm volatile("ldmatrix.sync.aligned.m8n8.x4.shared.b16 {%0,%1,%2,%3}, [%4];"
                 : "=r"(r0), "=r"(r1), "=r"(r2), "=r"(r3) : "r"(a));
}
__device__ __forceinline__ void ldmx4t(u32& r0, u32& r1, u32& r2, u32& r3, u32 a) {
    asm volatile("ldmatrix.sync.aligned.m8n8.x4.trans.shared.b16 {%0,%1,%2,%3}, [%4];"
                 : "=r"(r0), "=r"(r1), "=r"(r2), "=r"(r3) : "r"(a));
}
__device__ __forceinline__ void mma16816(float* c, const u32* a, u32 b0, u32 b1) {
    asm volatile(
        "mma.sync.aligned.m16n8k16.row.col.f32.bf16.bf16.f32 "
        "{%0,%1,%2,%3}, {%4,%5,%6,%7}, {%8,%9}, {%0,%1,%2,%3};"
        : "+f"(c[0]), "+f"(c[1]), "+f"(c[2]), "+f"(c[3])
        : "r"(a[0]), "r"(a[1]), "r"(a[2]), "r"(a[3]), "r"(b0), "r"(b1));
}

// ---------------------------------------------------------------------------
// Kernel 0: build fragment-linearized bf16 weight tables.
//   frag value for (tileReg iq, lane l): n += (iq>>1)*8 + l/4 ; k += (iq&1)*8 + 2*(l%4)
// ---------------------------------------------------------------------------
__global__ void prep_weights(const float* __restrict__ W, const float* __restrict__ Wo)
{
    const int i = blockIdx.x * 256 + threadIdx.x;   // 0..8191
    if (i < 6144) {          // W table
        const int lane = i & 31;
        const int iq   = (i >> 5) & 3;
        const int fu   = i >> 7;           // 0..47
        const int ks   = fu & 3;
        const int jpnc = fu >> 2;          // 0..11
        const int jp   = jpnc % 3;
        const int nc   = jpnc / 3;
        const int n = nc * 48 + jp * 16 + (iq >> 1) * 8 + (lane >> 2);
        const int k = ks * 16 + (iq & 1) * 8 + 2 * (lane & 3);
        g_wqf[i] = (u32)f2bf(W[k * 192 + n]) | ((u32)f2bf(W[(k + 1) * 192 + n]) << 16);
    } else if (i < 8192) {   // Wo table
        const int j = i - 6144;
        const int lane = j & 31;
        const int iq   = (j >> 5) & 3;
        const int fu   = j >> 7;           // 0..15
        const int ks   = fu & 3;
        const int jp   = fu >> 2;
        const int n = jp * 16 + (iq >> 1) * 8 + (lane >> 2);
        const int k = ks * 16 + (iq & 1) * 8 + 2 * (lane & 3);
        g_wof[j] = (u32)f2bf(Wo[k * 64 + n]) | ((u32)f2bf(Wo[(k + 1) * 64 + n]) << 16);
    }
}

// ---------------------------------------------------------------------------
// Fused kernel: one CTA per batch, 512 threads, 113.15KB smem -> 2 CTAs/SM.
// Phase 1: QKV = X@W (W frags via LDG) -> QKV smem, Q pre-scaled.
// Phase 2: FA2 attention; O (bf16) overwrites its own Q block in QKV smem.
// Phase 3: Y = O@Wo (Wo frags via LDG) + X ; in-register LN -> out.
//
// smem map (bytes):
//   [0,     29952)  X bf16 [208][72] stride 144
//   [29952,113152)  QKV bf16 [208][200] stride 400 (Q->O:0-63 K:64-127 V:128-191)
// ---------------------------------------------------------------------------
#define FU_X   0
#define FU_QKV 29952
#define FU_SMEM 113152

__global__ __launch_bounds__(512, 2)
void fused_mha(const float* __restrict__ X, const int* __restrict__ lens,
               const float* __restrict__ gamma, const float* __restrict__ beta,
               float* __restrict__ out)
{
    extern __shared__ char sm[];
    const u32 sb = smem_u32(sm);
    const int tid = threadIdx.x;
    const int b = blockIdx.x;
    const size_t rowg0 = (size_t)b * TT;

    // ---- stage X fp32 -> bf16 [208][72] ----
    {
        const float4* xs = (const float4*)(X + rowg0 * EE);
        for (int i = tid; i < 3200; i += 512) {
            float4 v = xs[i];
            const int r = i >> 4, q = i & 15;
            uint2 p;
            p.x = bfx2(v.x, v.y);
            p.y = bfx2(v.z, v.w);
            *(uint2*)(sm + FU_X + r * 144 + q * 8) = p;
        }
        if (tid < 72)   // zero pad rows 200..207
            *(uint4*)(sm + FU_X + 200 * 144 + tid * 16) = make_uint4(0, 0, 0, 0);
    }
    __syncthreads();

    const int lane = tid & 31;
    const int w    = tid >> 5;      // 0..15
    const int grp  = lane >> 3;
    const int qd   = lane & 3;

    int len = lens[b];
    if (len < 1) len = 1;
    if (len > TT) len = TT;
    const int kcnt = (len + 15) >> 4;
    const float CSC = 0.36067376022224085f;   // 0.25 * log2(e)

    // ================= Phase 1: QKV GEMM (52 tasks over 16 warps) ===========
    {
        const u32 a_off = (u32)(((grp & 1) * 8 + (lane & 7)) * 144 + (grp >> 1) * 16);

        for (int t = w; t < 52; t += 16) {
            const int mm = t % 13;        // row tile
            const int nc = t / 13;        // 48-col chunk
            if (nc >= 2 && mm >= kcnt) continue;   // K/V rows never read

            const u32 a_base = sb + FU_X + (u32)(mm * 16) * 144 + a_off;
            float acc[6][4];
            #pragma unroll
            for (int j = 0; j < 6; j++)
                #pragma unroll
                for (int q = 0; q < 4; q++) acc[j][q] = 0.f;

            #pragma unroll
            for (int ks = 0; ks < 4; ks++) {
                u32 A[4];
                ldmx4(A[0], A[1], A[2], A[3], a_base + (u32)(ks * 32));
                #pragma unroll
                for (int jp = 0; jp < 3; jp++) {
                    const u32* wf = g_wqf + ((nc * 3 + jp) * 4 + ks) * 128 + lane;
                    u32 Bh[4];
                    Bh[0] = wf[0];  Bh[1] = wf[32];
                    Bh[2] = wf[64]; Bh[3] = wf[96];
                    mma16816(acc[jp * 2],     A, Bh[0], Bh[1]);
                    mma16816(acc[jp * 2 + 1], A, Bh[2], Bh[3]);
                }
            }
            const int rA = mm * 16 + (lane >> 2);
            const int rB = rA + 8;
            #pragma unroll
            for (int j = 0; j < 6; j++) {
                const int c = nc * 48 + 8 * j + 2 * qd;
                const float sc = (c < UU) ? CSC : 1.0f;
                *(u32*)(sm + FU_QKV + rA * 400 + c * 2) =
                    bfx2(acc[j][0] * sc, acc[j][1] * sc);
                *(u32*)(sm + FU_QKV + rB * 400 + c * 2) =
                    bfx2(acc[j][2] * sc, acc[j][3] * sc);
            }
        }
    }
    __syncthreads();

    // ===== Phase 2: attention (52 tasks); O overwrites its own Q block =====
    {
        const u32 arow = (u32)(((grp & 1) * 8 + (lane & 7)) * 400 + (grp >> 1) * 16);
        const u32 krow = (u32)(((grp >> 1) * 8 + (lane & 7)) * 400 + (grp & 1) * 16);
        const u32 vrow = (u32)(((grp & 1) * 8 + (lane & 7)) * 400 + (grp >> 1) * 16);

        for (int t = w; t < 52; t += 16) {
            const int hh = t / 13;
            const int mm = t - hh * 13;
            const u32 hb = (u32)(hh * 32);

            u32 A[4];
            ldmx4(A[0], A[1], A[2], A[3],
                  sb + FU_QKV + (u32)(mm * 16) * 400 + hb + arow);
            const u32 ka = sb + FU_QKV + 128 + hb + krow;
            const u32 va = sb + FU_QKV + 256 + hb + vrow;

            float o0[4] = {0,0,0,0}, o1[4] = {0,0,0,0};
            ull lA = 0, lB = 0;

            for (int np = 0; np < kcnt; np++) {
                u32 KB[4], VB[4];
                ldmx4(KB[0], KB[1], KB[2], KB[3], ka + (u32)(np * 6400));
                ldmx4t(VB[0], VB[1], VB[2], VB[3], va + (u32)(np * 6400));

                const int c0 = np * 16 + 2 * qd;
                const ull m0 = pack2(c0 < len ? 1.f : 0.f, (c0 + 1) < len ? 1.f : 0.f);
                const ull m1 = pack2((c0 + 8) < len ? 1.f : 0.f, (c0 + 9) < len ? 1.f : 0.f);

                u32 aE[4];
                #pragma unroll
                for (int sub = 0; sub < 2; sub++) {
                    float s[4] = {0.f, 0.f, 0.f, 0.f};
                    mma16816(s, A, KB[sub * 2], KB[sub * 2 + 1]);
                    const ull m = sub ? m1 : m0;
                    const ull eA = fmul2(exp2p(pack2(s[0], s[1])), m);
                    const ull eB = fmul2(exp2p(pack2(s[2], s[3])), m);
                    lA = fadd2(lA, eA);
                    lB = fadd2(lB, eB);
                    aE[sub * 2]     = cvt_bf16x2p(eA);
                    aE[sub * 2 + 1] = cvt_bf16x2p(eB);
                }
                mma16816(o0, aE, VB[0], VB[1]);
                mma16816(o1, aE, VB[2], VB[3]);
            }

            // normalize + store O (bf16) over this task's Q block
            float x, y;
            unpack2(lA, x, y); float la = x + y;
            la += __shfl_xor_sync(0xFFFFFFFFu, la, 1);
            la += __shfl_xor_sync(0xFFFFFFFFu, la, 2);
            unpack2(lB, x, y); float lb = x + y;
            lb += __shfl_xor_sync(0xFFFFFFFFu, lb, 1);
            lb += __shfl_xor_sync(0xFFFFFFFFu, lb, 2);
            const float iA = 1.f / la, iB = 1.f / lb;
            const int cb = hh * 16 + 2 * qd;
            const int rA = mm * 16 + (lane >> 2), rB = rA + 8;
            if (rA < TT) {
                *(u32*)(sm + FU_QKV + rA * 400 + cb * 2)      = bfx2(o0[0] * iA, o0[1] * iA);
                *(u32*)(sm + FU_QKV + rA * 400 + cb * 2 + 16) = bfx2(o1[0] * iA, o1[1] * iA);
            }
            if (rB < TT) {
                *(u32*)(sm + FU_QKV + rB * 400 + cb * 2)      = bfx2(o0[2] * iB, o0[3] * iB);
                *(u32*)(sm + FU_QKV + rB * 400 + cb * 2 + 16) = bfx2(o1[2] * iB, o1[3] * iB);
            }
        }
    }
    __syncthreads();

    // ================= Phase 3: projection + residual + LN =================
    if (w < 13) {
        const u32 a_base = sb + FU_QKV +
            (u32)((w * 16 + (grp & 1) * 8 + (lane & 7)) * 400 + (grp >> 1) * 16);

        float acc[8][4];
        #pragma unroll
        for (int j = 0; j < 8; j++)
            #pragma unroll
            for (int q = 0; q < 4; q++) acc[j][q] = 0.f;

        #pragma unroll
        for (int ks = 0; ks < 4; ks++) {
            u32 Af[4];
            ldmx4(Af[0], Af[1], Af[2], Af[3], a_base + (u32)(ks * 32));
            #pragma unroll
            for (int jp = 0; jp < 4; jp++) {
                const u32* wf = g_wof + (jp * 4 + ks) * 128 + lane;
                u32 Bh[4];
                Bh[0] = wf[0];  Bh[1] = wf[32];
                Bh[2] = wf[64]; Bh[3] = wf[96];
                mma16816(acc[jp * 2],     Af, Bh[0], Bh[1]);
                mma16816(acc[jp * 2 + 1], Af, Bh[2], Bh[3]);
            }
        }

        const int rAl = w * 16 + (lane >> 2);
        const int rBl = rAl + 8;
        const bool okB = rBl < TT;
        const size_t rowA = rowg0 + rAl;
        const size_t rowB = rowg0 + rBl;
        const int cq = 2 * qd;

        #pragma unroll
        for (int j = 0; j < 8; j++) {
            const int c = 8 * j + cq;
            float2 xa = *(const float2*)(X + rowA * UU + c);
            acc[j][0] += xa.x; acc[j][1] += xa.y;
            if (okB) {
                float2 xb = *(const float2*)(X + rowB * UU + c);
                acc[j][2] += xb.x; acc[j][3] += xb.y;
            }
        }

        float sA = 0.f, sB = 0.f;
        #pragma unroll
        for (int j = 0; j < 8; j++) {
            sA += acc[j][0] + acc[j][1];
            sB += acc[j][2] + acc[j][3];
        }
        sA += __shfl_xor_sync(0xFFFFFFFFu, sA, 1);
        sA += __shfl_xor_sync(0xFFFFFFFFu, sA, 2);
        sB += __shfl_xor_sync(0xFFFFFFFFu, sB, 1);
        sB += __shfl_xor_sync(0xFFFFFFFFu, sB, 2);
        const float mA = sA * (1.0f / 64.0f);
        const float mB = sB * (1.0f / 64.0f);

        float vA = 0.f, vB = 0.f;
        #pragma unroll
        for (int j = 0; j < 8; j++) {
            float d0 = acc[j][0] - mA, d1 = acc[j][1] - mA;
            float d2 = acc[j][2] - mB, d3 = acc[j][3] - mB;
            vA = fmaf(d0, d0, fmaf(d1, d1, vA));
            vB = fmaf(d2, d2, fmaf(d3, d3, vB));
        }
        vA += __shfl_xor_sync(0xFFFFFFFFu, vA, 1);
        vA += __shfl_xor_sync(0xFFFFFFFFu, vA, 2);
        vB += __shfl_xor_sync(0xFFFFFFFFu, vB, 1);
        vB += __shfl_xor_sync(0xFFFFFFFFu, vB, 2);
        const float iA = rsqrtf(vA * (1.0f / 64.0f) + 1e-9f);
        const float iB = rsqrtf(vB * (1.0f / 64.0f) + 1e-9f);

        #pragma unroll
        for (int j = 0; j < 8; j++) {
            const int c = 8 * j + cq;
            const float2 gg = *(const float2*)(gamma + c);
            const float2 bb = *(const float2*)(beta + c);
            float2 oa;
            oa.x = fmaf((acc[j][0] - mA) * iA, gg.x, bb.x);
            oa.y = fmaf((acc[j][1] - mA) * iA, gg.y, bb.y);
            *(float2*)(out + rowA * UU + c) = oa;
            if (okB) {
                float2 ob;
                ob.x = fmaf((acc[j][2] - mB) * iB, gg.x, bb.x);
                ob.y = fmaf((acc[j][3] - mB) * iB, gg.y, bb.y);
                *(float2*)(out + rowB * UU + c) = ob;
            }
        }
    }
}

// ---------------------------------------------------------------------------
extern "C" void kernel_launch(void* const* d_in, const int* in_sizes, int n_in,
                              void* d_out, int out_size)
{
    const float* input_info = (const float*)d_in[0];
    const int*   keys_len   = (const int*)d_in[1];
    const float* W          = (const float*)d_in[2];
    const float* W_output   = (const float*)d_in[3];
    const float* gamma      = (const float*)d_in[4];
    const float* beta       = (const float*)d_in[5];
    float* out = (float*)d_out;

    cudaFuncSetAttribute(fused_mha, cudaFuncAttributeMaxDynamicSharedMemorySize, FU_SMEM);

    prep_weights<<<32, 256>>>(W, W_output);
    fused_mha<<<BB, 512, FU_SMEM>>>(input_info, keys_len, gamma, beta, out);
}

// round 15
// speedup vs baseline: 1.3164x; 1.0745x over previous
#include <cuda_runtime.h>
#include <math.h>

#define BB 1024
#define TT 200
#define EE 64
#define UU 64
#define HH 4
#define DH 16
#define C3U 192

typedef unsigned long long ull;
typedef unsigned int u32;
typedef unsigned short u16;

// Fragment-linearized weight tables (exact ldmatrix lane results).
// g_wqf: phase-1 W frags (Q cols pre-scaled by 0.25*log2e)
// g_wof: phase-3 Wo frags
__device__ __align__(16) u32 g_wqf[6144];
__device__ __align__(16) u32 g_wof[2048];

// ---------------------------------------------------------------------------
__device__ __forceinline__ u16 f2bf(float f) {
    u32 u = __float_as_uint(f);
    u32 r = u + 0x7FFFu + ((u >> 16) & 1u);
    return (u16)(r >> 16);
}
__device__ __forceinline__ u32 bfx2(float lo, float hi) {
    u32 r; asm("cvt.rn.bf16x2.f32 %0, %1, %2;" : "=r"(r) : "f"(hi), "f"(lo));
    return r;
}
__device__ __forceinline__ ull pack2(float x, float y) {
    ull r; asm("mov.b64 %0, {%1, %2};" : "=l"(r) : "f"(x), "f"(y)); return r;
}
__device__ __forceinline__ void unpack2(ull v, float& x, float& y) {
    asm("mov.b64 {%0, %1}, %2;" : "=f"(x), "=f"(y) : "l"(v));
}
__device__ __forceinline__ ull ffma2(ull a, ull b, ull c) {
    ull d; asm("fma.rn.f32x2 %0, %1, %2, %3;" : "=l"(d) : "l"(a), "l"(b), "l"(c)); return d;
}
__device__ __forceinline__ ull fmul2(ull a, ull b) {
    ull d; asm("mul.rn.f32x2 %0, %1, %2;" : "=l"(d) : "l"(a), "l"(b)); return d;
}
__device__ __forceinline__ ull fadd2(ull a, ull b) {
    ull d; asm("add.rn.f32x2 %0, %1, %2;" : "=l"(d) : "l"(a), "l"(b)); return d;
}

// packed 2^y (y already log2-scaled); degree-4 poly (err<=4.2e-5, << bf16-P noise)
__device__ __forceinline__ ull exp2p(ull y2) {
    const float BIG = 12582912.0f;
    ull t2  = fadd2(y2, pack2(BIG, BIG));
    ull nf2 = fadd2(t2, pack2(-BIG, -BIG));
    ull r2  = ffma2(nf2, pack2(-1.f, -1.f), y2);
    ull p2  = ffma2(pack2(0.00961812911f, 0.00961812911f), r2,
                    pack2(0.0555041087f, 0.0555041087f));
    p2 = ffma2(p2, r2, pack2(0.240226507f, 0.240226507f));
    p2 = ffma2(p2, r2, pack2(0.693147182f, 0.693147182f));
    p2 = ffma2(p2, r2, pack2(1.f, 1.f));
    float pa, pb, ta, tb;
    unpack2(p2, pa, pb);
    unpack2(t2, ta, tb);
    const float e0 = __int_as_float(__float_as_int(pa) + (__float_as_int(ta) << 23));
    const float e1 = __int_as_float(__float_as_int(pb) + (__float_as_int(tb) << 23));
    return pack2(e0, e1);
}
__device__ __forceinline__ u32 cvt_bf16x2p(ull e2) {
    float x, y; unpack2(e2, x, y);
    return bfx2(x, y);
}

// ---------------------------------------------------------------------------
__device__ __forceinline__ u32 smem_u32(const void* p) {
    u32 a; asm("{ .reg .u64 t; cvta.to.shared.u64 t, %1; cvt.u32.u64 %0, t; }"
               : "=r"(a) : "l"(p));
    return a;
}
__device__ __forceinline__ void ldmx4(u32& r0, u32& r1, u32& r2, u32& r3, u32 a) {
    asm volatile("ldmatrix.sync.aligned.m8n8.x4.shared.b16 {%0,%1,%2,%3}, [%4];"
                 : "=r"(r0), "=r"(r1), "=r"(r2), "=r"(r3) : "r"(a));
}
__device__ __forceinline__ void ldmx4t(u32& r0, u32& r1, u32& r2, u32& r3, u32 a) {
    asm volatile("ldmatrix.sync.aligned.m8n8.x4.trans.shared.b16 {%0,%1,%2,%3}, [%4];"
                 : "=r"(r0), "=r"(r1), "=r"(r2), "=r"(r3) : "r"(a));
}
__device__ __forceinline__ void mma16816(float* c, const u32* a, u32 b0, u32 b1) {
    asm volatile(
        "mma.sync.aligned.m16n8k16.row.col.f32.bf16.bf16.f32 "
        "{%0,%1,%2,%3}, {%4,%5,%6,%7}, {%8,%9}, {%0,%1,%2,%3};"
        : "+f"(c[0]), "+f"(c[1]), "+f"(c[2]), "+f"(c[3])
        : "r"(a[0]), "r"(a[1]), "r"(a[2]), "r"(a[3]), "r"(b0), "r"(b1));
}

// ---------------------------------------------------------------------------
// Kernel 0: build fragment-linearized bf16 weight tables.
// Q columns (n<64) of W pre-scaled by 0.25*log2(e).
// ---------------------------------------------------------------------------
__global__ void prep_weights(const float* __restrict__ W, const float* __restrict__ Wo)
{
    const float CSC = 0.36067376022224085f;
    const int i = blockIdx.x * 256 + threadIdx.x;   // 0..8191
    if (i < 6144) {          // W table
        const int lane = i & 31;
        const int iq   = (i >> 5) & 3;
        const int fu   = i >> 7;           // 0..47
        const int ks   = fu & 3;
        const int jpnc = fu >> 2;          // 0..11
        const int jp   = jpnc % 3;
        const int nc   = jpnc / 3;
        const int n = nc * 48 + jp * 16 + (iq >> 1) * 8 + (lane >> 2);
        const int k = ks * 16 + (iq & 1) * 8 + 2 * (lane & 3);
        const float sc = (n < UU) ? CSC : 1.0f;
        g_wqf[i] = (u32)f2bf(W[k * 192 + n] * sc) |
                   ((u32)f2bf(W[(k + 1) * 192 + n] * sc) << 16);
    } else if (i < 8192) {   // Wo table
        const int j = i - 6144;
        const int lane = j & 31;
        const int iq   = (j >> 5) & 3;
        const int fu   = j >> 7;           // 0..15
        const int ks   = fu & 3;
        const int jp   = fu >> 2;
        const int n = jp * 16 + (iq >> 1) * 8 + (lane >> 2);
        const int k = ks * 16 + (iq & 1) * 8 + 2 * (lane & 3);
        g_wof[j] = (u32)f2bf(Wo[k * 64 + n]) | ((u32)f2bf(Wo[(k + 1) * 64 + n]) << 16);
    }
}

// ---------------------------------------------------------------------------
// Fused kernel: one CTA per batch, 512 threads, 113.15KB smem -> 2 CTAs/SM.
// smem: [0,29952) X bf16 [208][72]; [29952,113152) QKV [208][200] stride 400
// ---------------------------------------------------------------------------
#define FU_X   0
#define FU_QKV 29952
#define FU_SMEM 113152

__global__ __launch_bounds__(512, 2)
void fused_mha(const float* __restrict__ X, const int* __restrict__ lens,
               const float* __restrict__ gamma, const float* __restrict__ beta,
               float* __restrict__ out)
{
    extern __shared__ char sm[];
    const u32 sb = smem_u32(sm);
    const int tid = threadIdx.x;
    const int b = blockIdx.x;
    const size_t rowg0 = (size_t)b * TT;

    // ---- stage X fp32 -> bf16 [208][72] ----
    {
        const float4* xs = (const float4*)(X + rowg0 * EE);
        for (int i = tid; i < 3200; i += 512) {
            float4 v = xs[i];
            const int r = i >> 4, q = i & 15;
            uint2 p;
            p.x = bfx2(v.x, v.y);
            p.y = bfx2(v.z, v.w);
            *(uint2*)(sm + FU_X + r * 144 + q * 8) = p;
        }
        if (tid < 72)   // zero pad rows 200..207
            *(uint4*)(sm + FU_X + 200 * 144 + tid * 16) = make_uint4(0, 0, 0, 0);
    }
    __syncthreads();

    const int lane = tid & 31;
    const int w    = tid >> 5;      // 0..15
    const int grp  = lane >> 3;
    const int qd   = lane & 3;

    int len = lens[b];
    if (len < 1) len = 1;
    if (len > TT) len = TT;
    const int kcnt = (len + 15) >> 4;

    // ================= Phase 1: QKV GEMM (52 tasks over 16 warps) ===========
    {
        const u32 a_off = (u32)(((grp & 1) * 8 + (lane & 7)) * 144 + (grp >> 1) * 16);

        for (int t = w; t < 52; t += 16) {
            const int mm = t % 13;        // row tile
            const int nc = t / 13;        // 48-col chunk
            if (nc >= 2 && mm >= kcnt) continue;   // K/V rows never read

            const u32 a_base = sb + FU_X + (u32)(mm * 16) * 144 + a_off;
            float acc[6][4];
            #pragma unroll
            for (int j = 0; j < 6; j++)
                #pragma unroll
                for (int q = 0; q < 4; q++) acc[j][q] = 0.f;

            #pragma unroll
            for (int ks = 0; ks < 4; ks++) {
                u32 A[4];
                ldmx4(A[0], A[1], A[2], A[3], a_base + (u32)(ks * 32));
                #pragma unroll
                for (int jp = 0; jp < 3; jp++) {
                    const u32* wf = g_wqf + ((nc * 3 + jp) * 4 + ks) * 128 + lane;
                    u32 Bh[4];
                    Bh[0] = wf[0];  Bh[1] = wf[32];
                    Bh[2] = wf[64]; Bh[3] = wf[96];
                    mma16816(acc[jp * 2],     A, Bh[0], Bh[1]);
                    mma16816(acc[jp * 2 + 1], A, Bh[2], Bh[3]);
                }
            }
            const int rA = mm * 16 + (lane >> 2);
            const int rB = rA + 8;
            #pragma unroll
            for (int j = 0; j < 6; j++) {
                const int c = nc * 48 + 8 * j + 2 * qd;
                *(u32*)(sm + FU_QKV + rA * 400 + c * 2) = bfx2(acc[j][0], acc[j][1]);
                *(u32*)(sm + FU_QKV + rB * 400 + c * 2) = bfx2(acc[j][2], acc[j][3]);
            }
        }
    }
    __syncthreads();

    // ===== Phase 2: attention (52 tasks); O overwrites its own Q block =====
    {
        const u32 arow = (u32)(((grp & 1) * 8 + (lane & 7)) * 400 + (grp >> 1) * 16);
        const u32 krow = (u32)(((grp >> 1) * 8 + (lane & 7)) * 400 + (grp & 1) * 16);
        const u32 vrow = (u32)(((grp & 1) * 8 + (lane & 7)) * 400 + (grp >> 1) * 16);

        for (int t = w; t < 52; t += 16) {
            const int hh = t / 13;
            const int mm = t - hh * 13;
            const u32 hb = (u32)(hh * 32);

            u32 A[4];
            ldmx4(A[0], A[1], A[2], A[3],
                  sb + FU_QKV + (u32)(mm * 16) * 400 + hb + arow);
            const u32 ka = sb + FU_QKV + 128 + hb + krow;
            const u32 va = sb + FU_QKV + 256 + hb + vrow;

            float o0[4] = {0,0,0,0}, o1[4] = {0,0,0,0};
            ull lA = 0, lB = 0;

            // ---- full (unmasked) chunks 0..kcnt-2 ----
            for (int np = 0; np < kcnt - 1; np++) {
                u32 KB[4], VB[4];
                ldmx4(KB[0], KB[1], KB[2], KB[3], ka + (u32)(np * 6400));
                ldmx4t(VB[0], VB[1], VB[2], VB[3], va + (u32)(np * 6400));

                u32 aE[4];
                #pragma unroll
                for (int sub = 0; sub < 2; sub++) {
                    float s[4] = {0.f, 0.f, 0.f, 0.f};
                    mma16816(s, A, KB[sub * 2], KB[sub * 2 + 1]);
                    const ull eA = exp2p(pack2(s[0], s[1]));
                    const ull eB = exp2p(pack2(s[2], s[3]));
                    lA = fadd2(lA, eA);
                    lB = fadd2(lB, eB);
                    aE[sub * 2]     = cvt_bf16x2p(eA);
                    aE[sub * 2 + 1] = cvt_bf16x2p(eB);
                }
                mma16816(o0, aE, VB[0], VB[1]);
                mma16816(o1, aE, VB[2], VB[3]);
            }
            // ---- final (masked) chunk ----
            {
                const int np = kcnt - 1;
                u32 KB[4], VB[4];
                ldmx4(KB[0], KB[1], KB[2], KB[3], ka + (u32)(np * 6400));
                ldmx4t(VB[0], VB[1], VB[2], VB[3], va + (u32)(np * 6400));

                const int c0 = np * 16 + 2 * qd;
                const ull m0 = pack2(c0 < len ? 1.f : 0.f, (c0 + 1) < len ? 1.f : 0.f);
                const ull m1 = pack2((c0 + 8) < len ? 1.f : 0.f, (c0 + 9) < len ? 1.f : 0.f);

                u32 aE[4];
                #pragma unroll
                for (int sub = 0; sub < 2; sub++) {
                    float s[4] = {0.f, 0.f, 0.f, 0.f};
                    mma16816(s, A, KB[sub * 2], KB[sub * 2 + 1]);
                    const ull m = sub ? m1 : m0;
                    const ull eA = fmul2(exp2p(pack2(s[0], s[1])), m);
                    const ull eB = fmul2(exp2p(pack2(s[2], s[3])), m);
                    lA = fadd2(lA, eA);
                    lB = fadd2(lB, eB);
                    aE[sub * 2]     = cvt_bf16x2p(eA);
                    aE[sub * 2 + 1] = cvt_bf16x2p(eB);
                }
                mma16816(o0, aE, VB[0], VB[1]);
                mma16816(o1, aE, VB[2], VB[3]);
            }

            // normalize + store O (bf16) over this task's Q block
            float x, y;
            unpack2(lA, x, y); float la = x + y;
            la += __shfl_xor_sync(0xFFFFFFFFu, la, 1);
            la += __shfl_xor_sync(0xFFFFFFFFu, la, 2);
            unpack2(lB, x, y); float lb = x + y;
            lb += __shfl_xor_sync(0xFFFFFFFFu, lb, 1);
            lb += __shfl_xor_sync(0xFFFFFFFFu, lb, 2);
            const float iA = 1.f / la, iB = 1.f / lb;
            const int cb = hh * 16 + 2 * qd;
            const int rA = mm * 16 + (lane >> 2), rB = rA + 8;
            if (rA < TT) {
                *(u32*)(sm + FU_QKV + rA * 400 + cb * 2)      = bfx2(o0[0] * iA, o0[1] * iA);
                *(u32*)(sm + FU_QKV + rA * 400 + cb * 2 + 16) = bfx2(o1[0] * iA, o1[1] * iA);
            }
            if (rB < TT) {
                *(u32*)(sm + FU_QKV + rB * 400 + cb * 2)      = bfx2(o0[2] * iB, o0[3] * iB);
                *(u32*)(sm + FU_QKV + rB * 400 + cb * 2 + 16) = bfx2(o1[2] * iB, o1[3] * iB);
            }
        }
    }
    __syncthreads();

    // ================= Phase 3: projection + residual + LN =================
    if (w < 13) {
        const u32 a_base = sb + FU_QKV +
            (u32)((w * 16 + (grp & 1) * 8 + (lane & 7)) * 400 + (grp >> 1) * 16);

        float acc[8][4];
        #pragma unroll
        for (int j = 0; j < 8; j++)
            #pragma unroll
            for (int q = 0; q < 4; q++) acc[j][q] = 0.f;

        #pragma unroll
        for (int ks = 0; ks < 4; ks++) {
            u32 Af[4];
            ldmx4(Af[0], Af[1], Af[2], Af[3], a_base + (u32)(ks * 32));
            #pragma unroll
            for (int jp = 0; jp < 4; jp++) {
                const u32* wf = g_wof + (jp * 4 + ks) * 128 + lane;
                u32 Bh[4];
                Bh[0] = wf[0];  Bh[1] = wf[32];
                Bh[2] = wf[64]; Bh[3] = wf[96];
                mma16816(acc[jp * 2],     Af, Bh[0], Bh[1]);
                mma16816(acc[jp * 2 + 1], Af, Bh[2], Bh[3]);
            }
        }

        const int rAl = w * 16 + (lane >> 2);
        const int rBl = rAl + 8;
        const bool okB = rBl < TT;
        const size_t rowA = rowg0 + rAl;
        const size_t rowB = rowg0 + rBl;
        const int cq = 2 * qd;

        #pragma unroll
        for (int j = 0; j < 8; j++) {
            const int c = 8 * j + cq;
            float2 xa = *(const float2*)(X + rowA * UU + c);
            acc[j][0] += xa.x; acc[j][1] += xa.y;
            if (okB) {
                float2 xb = *(const float2*)(X + rowB * UU + c);
                acc[j][2] += xb.x; acc[j][3] += xb.y;
            }
        }

        float sA = 0.f, sB = 0.f;
        #pragma unroll
        for (int j = 0; j < 8; j++) {
            sA += acc[j][0] + acc[j][1];
            sB += acc[j][2] + acc[j][3];
        }
        sA += __shfl_xor_sync(0xFFFFFFFFu, sA, 1);
        sA += __shfl_xor_sync(0xFFFFFFFFu, sA, 2);
        sB += __shfl_xor_sync(0xFFFFFFFFu, sB, 1);
        sB += __shfl_xor_sync(0xFFFFFFFFu, sB, 2);
        const float mA = sA * (1.0f / 64.0f);
        const float mB = sB * (1.0f / 64.0f);

        float vA = 0.f, vB = 0.f;
        #pragma unroll
        for (int j = 0; j < 8; j++) {
            float d0 = acc[j][0] - mA, d1 = acc[j][1] - mA;
            float d2 = acc[j][2] - mB, d3 = acc[j][3] - mB;
            vA = fmaf(d0, d0, fmaf(d1, d1, vA));
            vB = fmaf(d2, d2, fmaf(d3, d3, vB));
        }
        vA += __shfl_xor_sync(0xFFFFFFFFu, vA, 1);
        vA += __shfl_xor_sync(0xFFFFFFFFu, vA, 2);
        vB += __shfl_xor_sync(0xFFFFFFFFu, vB, 1);
        vB += __shfl_xor_sync(0xFFFFFFFFu, vB, 2);
        const float iA = rsqrtf(vA * (1.0f / 64.0f) + 1e-9f);
        const float iB = rsqrtf(vB * (1.0f / 64.0f) + 1e-9f);

        #pragma unroll
        for (int j = 0; j < 8; j++) {
            const int c = 8 * j + cq;
            const float2 gg = *(const float2*)(gamma + c);
            const float2 bb = *(const float2*)(beta + c);
            float2 oa;
            oa.x = fmaf((acc[j][0] - mA) * iA, gg.x, bb.x);
            oa.y = fmaf((acc[j][1] - mA) * iA, gg.y, bb.y);
            *(float2*)(out + rowA * UU + c) = oa;
            if (okB) {
                float2 ob;
                ob.x = fmaf((acc[j][2] - mB) * iB, gg.x, bb.x);
                ob.y = fmaf((acc[j][3] - mB) * iB, gg.y, bb.y);
                *(float2*)(out + rowB * UU + c) = ob;
            }
        }
    }
}

// ---------------------------------------------------------------------------
extern "C" void kernel_launch(void* const* d_in, const int* in_sizes, int n_in,
                              void* d_out, int out_size)
{
    const float* input_info = (const float*)d_in[0];
    const int*   keys_len   = (const int*)d_in[1];
    const float* W          = (const float*)d_in[2];
    const float* W_output   = (const float*)d_in[3];
    const float* gamma      = (const float*)d_in[4];
    const float* beta       = (const float*)d_in[5];
    float* out = (float*)d_out;

    cudaFuncSetAttribute(fused_mha, cudaFuncAttributeMaxDynamicSharedMemorySize, FU_SMEM);

    prep_weights<<<32, 256>>>(W, W_output);
    fused_mha<<<BB, 512, FU_SMEM>>>(input_info, keys_len, gamma, beta, out);
}

// round 16
// speedup vs baseline: 1.4878x; 1.1302x over previous
#include <cuda_runtime.h>
#include <math.h>

#define BB 1024
#define TT 200
#define EE 64
#define UU 64
#define HH 4
#define DH 16
#define C3U 192

typedef unsigned long long ull;
typedef unsigned int u32;
typedef unsigned short u16;

// Fragment-linearized weight tables (exact ldmatrix lane results).
__device__ __align__(16) u32 g_wqf[6144];   // W frags (Q cols pre-scaled by 0.25*log2e)
__device__ __align__(16) u32 g_wof[2048];   // Wo frags

// ---------------------------------------------------------------------------
__device__ __forceinline__ u16 f2bf(float f) {
    u32 u = __float_as_uint(f);
    u32 r = u + 0x7FFFu + ((u >> 16) & 1u);
    return (u16)(r >> 16);
}
__device__ __forceinline__ u32 bfx2(float lo, float hi) {
    u32 r; asm("cvt.rn.bf16x2.f32 %0, %1, %2;" : "=r"(r) : "f"(hi), "f"(lo));
    return r;
}
__device__ __forceinline__ float ex2f(float x) {   // MUFU.EX2 (own pipe)
    float r; asm("ex2.approx.f32 %0, %1;" : "=f"(r) : "f"(x));
    return r;
}

// ---------------------------------------------------------------------------
__device__ __forceinline__ u32 smem_u32(const void* p) {
    u32 a; asm("{ .reg .u64 t; cvta.to.shared.u64 t, %1; cvt.u32.u64 %0, t; }"
               : "=r"(a) : "l"(p));
    return a;
}
__device__ __forceinline__ void ldmx4(u32& r0, u32& r1, u32& r2, u32& r3, u32 a) {
    asm volatile("ldmatrix.sync.aligned.m8n8.x4.shared.b16 {%0,%1,%2,%3}, [%4];"
                 : "=r"(r0), "=r"(r1), "=r"(r2), "=r"(r3) : "r"(a));
}
__device__ __forceinline__ void ldmx4t(u32& r0, u32& r1, u32& r2, u32& r3, u32 a) {
    asm volatile("ldmatrix.sync.aligned.m8n8.x4.trans.shared.b16 {%0,%1,%2,%3}, [%4];"
                 : "=r"(r0), "=r"(r1), "=r"(r2), "=r"(r3) : "r"(a));
}
__device__ __forceinline__ void mma16816(float* c, const u32* a, u32 b0, u32 b1) {
    asm volatile(
        "mma.sync.aligned.m16n8k16.row.col.f32.bf16.bf16.f32 "
        "{%0,%1,%2,%3}, {%4,%5,%6,%7}, {%8,%9}, {%0,%1,%2,%3};"
        : "+f"(c[0]), "+f"(c[1]), "+f"(c[2]), "+f"(c[3])
        : "r"(a[0]), "r"(a[1]), "r"(a[2]), "r"(a[3]), "r"(b0), "r"(b1));
}

// ---------------------------------------------------------------------------
// Kernel 0: build fragment-linearized bf16 weight tables.
// Q columns (n<64) of W pre-scaled by 0.25*log2(e).
// ---------------------------------------------------------------------------
__global__ void prep_weights(const float* __restrict__ W, const float* __restrict__ Wo)
{
    const float CSC = 0.36067376022224085f;
    const int i = blockIdx.x * 256 + threadIdx.x;   // 0..8191
    if (i < 6144) {          // W table
        const int lane = i & 31;
        const int iq   = (i >> 5) & 3;
        const int fu   = i >> 7;           // 0..47
        const int ks   = fu & 3;
        const int jpnc = fu >> 2;          // 0..11
        const int jp   = jpnc % 3;
        const int nc   = jpnc / 3;
        const int n = nc * 48 + jp * 16 + (iq >> 1) * 8 + (lane >> 2);
        const int k = ks * 16 + (iq & 1) * 8 + 2 * (lane & 3);
        const float sc = (n < UU) ? CSC : 1.0f;
        g_wqf[i] = (u32)f2bf(W[k * 192 + n] * sc) |
                   ((u32)f2bf(W[(k + 1) * 192 + n] * sc) << 16);
    } else if (i < 8192) {   // Wo table
        const int j = i - 6144;
        const int lane = j & 31;
        const int iq   = (j >> 5) & 3;
        const int fu   = j >> 7;           // 0..15
        const int ks   = fu & 3;
        const int jp   = fu >> 2;
        const int n = jp * 16 + (iq >> 1) * 8 + (lane >> 2);
        const int k = ks * 16 + (iq & 1) * 8 + 2 * (lane & 3);
        g_wof[j] = (u32)f2bf(Wo[k * 64 + n]) | ((u32)f2bf(Wo[(k + 1) * 64 + n]) << 16);
    }
}

// ---------------------------------------------------------------------------
// Fused kernel: one CTA per batch, 512 threads, 113.15KB smem -> 2 CTAs/SM.
// smem: [0,29952) X bf16 [208][72]; [29952,113152) QKV [208][200] stride 400
// ---------------------------------------------------------------------------
#define FU_X   0
#define FU_QKV 29952
#define FU_SMEM 113152

__global__ __launch_bounds__(512, 2)
void fused_mha(const float* __restrict__ X, const int* __restrict__ lens,
               const float* __restrict__ gamma, const float* __restrict__ beta,
               float* __restrict__ out)
{
    extern __shared__ char sm[];
    const u32 sb = smem_u32(sm);
    const int tid = threadIdx.x;
    const int b = blockIdx.x;
    const size_t rowg0 = (size_t)b * TT;

    // ---- stage X fp32 -> bf16 [208][72] ----
    {
        const float4* xs = (const float4*)(X + rowg0 * EE);
        for (int i = tid; i < 3200; i += 512) {
            float4 v = xs[i];
            const int r = i >> 4, q = i & 15;
            uint2 p;
            p.x = bfx2(v.x, v.y);
            p.y = bfx2(v.z, v.w);
            *(uint2*)(sm + FU_X + r * 144 + q * 8) = p;
        }
        if (tid < 72)   // zero pad rows 200..207
            *(uint4*)(sm + FU_X + 200 * 144 + tid * 16) = make_uint4(0, 0, 0, 0);
    }
    __syncthreads();

    const int lane = tid & 31;
    const int w    = tid >> 5;      // 0..15
    const int grp  = lane >> 3;
    const int qd   = lane & 3;

    int len = lens[b];
    if (len < 1) len = 1;
    if (len > TT) len = TT;
    const int kcnt = (len + 15) >> 4;

    // ================= Phase 1: QKV GEMM (52 tasks over 16 warps) ===========
    {
        const u32 a_off = (u32)(((grp & 1) * 8 + (lane & 7)) * 144 + (grp >> 1) * 16);

        for (int t = w; t < 52; t += 16) {
            const int mm = t % 13;        // row tile
            const int nc = t / 13;        // 48-col chunk
            if (nc >= 2 && mm >= kcnt) continue;   // K/V rows never read

            const u32 a_base = sb + FU_X + (u32)(mm * 16) * 144 + a_off;
            float acc[6][4];
            #pragma unroll
            for (int j = 0; j < 6; j++)
                #pragma unroll
                for (int q = 0; q < 4; q++) acc[j][q] = 0.f;

            #pragma unroll
            for (int ks = 0; ks < 4; ks++) {
                u32 A[4];
                ldmx4(A[0], A[1], A[2], A[3], a_base + (u32)(ks * 32));
                #pragma unroll
                for (int jp = 0; jp < 3; jp++) {
                    const u32* wf = g_wqf + ((nc * 3 + jp) * 4 + ks) * 128 + lane;
                    u32 Bh[4];
                    Bh[0] = wf[0];  Bh[1] = wf[32];
                    Bh[2] = wf[64]; Bh[3] = wf[96];
                    mma16816(acc[jp * 2],     A, Bh[0], Bh[1]);
                    mma16816(acc[jp * 2 + 1], A, Bh[2], Bh[3]);
                }
            }
            const int rA = mm * 16 + (lane >> 2);
            const int rB = rA + 8;
            #pragma unroll
            for (int j = 0; j < 6; j++) {
                const int c = nc * 48 + 8 * j + 2 * qd;
                *(u32*)(sm + FU_QKV + rA * 400 + c * 2) = bfx2(acc[j][0], acc[j][1]);
                *(u32*)(sm + FU_QKV + rB * 400 + c * 2) = bfx2(acc[j][2], acc[j][3]);
            }
        }
    }
    __syncthreads();

    // ===== Phase 2: attention (52 tasks); exp via MUFU.EX2; O over Q block ==
    {
        const u32 arow = (u32)(((grp & 1) * 8 + (lane & 7)) * 400 + (grp >> 1) * 16);
        const u32 krow = (u32)(((grp >> 1) * 8 + (lane & 7)) * 400 + (grp & 1) * 16);
        const u32 vrow = (u32)(((grp & 1) * 8 + (lane & 7)) * 400 + (grp >> 1) * 16);

        for (int t = w; t < 52; t += 16) {
            const int hh = t / 13;
            const int mm = t - hh * 13;
            const u32 hb = (u32)(hh * 32);

            u32 A[4];
            ldmx4(A[0], A[1], A[2], A[3],
                  sb + FU_QKV + (u32)(mm * 16) * 400 + hb + arow);
            const u32 ka = sb + FU_QKV + 128 + hb + krow;
            const u32 va = sb + FU_QKV + 256 + hb + vrow;

            float o0[4] = {0,0,0,0}, o1[4] = {0,0,0,0};
            float la = 0.f, lb = 0.f;

            // ---- full (unmasked) chunks 0..kcnt-2 ----
            for (int np = 0; np < kcnt - 1; np++) {
                u32 KB[4], VB[4];
                ldmx4(KB[0], KB[1], KB[2], KB[3], ka + (u32)(np * 6400));
                ldmx4t(VB[0], VB[1], VB[2], VB[3], va + (u32)(np * 6400));

                u32 aE[4];
                #pragma unroll
                for (int sub = 0; sub < 2; sub++) {
                    float s[4] = {0.f, 0.f, 0.f, 0.f};
                    mma16816(s, A, KB[sub * 2], KB[sub * 2 + 1]);
                    const float e0 = ex2f(s[0]);
                    const float e1 = ex2f(s[1]);
                    const float e2 = ex2f(s[2]);
                    const float e3 = ex2f(s[3]);
                    la += e0 + e1;
                    lb += e2 + e3;
                    aE[sub * 2]     = bfx2(e0, e1);
                    aE[sub * 2 + 1] = bfx2(e2, e3);
                }
                mma16816(o0, aE, VB[0], VB[1]);
                mma16816(o1, aE, VB[2], VB[3]);
            }
            // ---- final (masked) chunk ----
            {
                const int np = kcnt - 1;
                u32 KB[4], VB[4];
                ldmx4(KB[0], KB[1], KB[2], KB[3], ka + (u32)(np * 6400));
                ldmx4t(VB[0], VB[1], VB[2], VB[3], va + (u32)(np * 6400));

                const int c0 = np * 16 + 2 * qd;
                const float mk[4] = {
                    (c0     < len) ? 1.f : 0.f,   // sub0 even col
                    (c0 + 1 < len) ? 1.f : 0.f,   // sub0 odd col
                    (c0 + 8 < len) ? 1.f : 0.f,   // sub1 even col
                    (c0 + 9 < len) ? 1.f : 0.f }; // sub1 odd col

                u32 aE[4];
                #pragma unroll
                for (int sub = 0; sub < 2; sub++) {
                    float s[4] = {0.f, 0.f, 0.f, 0.f};
                    mma16816(s, A, KB[sub * 2], KB[sub * 2 + 1]);
                    const float me = mk[sub * 2], mo = mk[sub * 2 + 1];
                    const float e0 = ex2f(s[0]) * me;
                    const float e1 = ex2f(s[1]) * mo;
                    const float e2 = ex2f(s[2]) * me;
                    const float e3 = ex2f(s[3]) * mo;
                    la += e0 + e1;
                    lb += e2 + e3;
                    aE[sub * 2]     = bfx2(e0, e1);
                    aE[sub * 2 + 1] = bfx2(e2, e3);
                }
                mma16816(o0, aE, VB[0], VB[1]);
                mma16816(o1, aE, VB[2], VB[3]);
            }

            // normalize + store O (bf16) over this task's Q block
            la += __shfl_xor_sync(0xFFFFFFFFu, la, 1);
            la += __shfl_xor_sync(0xFFFFFFFFu, la, 2);
            lb += __shfl_xor_sync(0xFFFFFFFFu, lb, 1);
            lb += __shfl_xor_sync(0xFFFFFFFFu, lb, 2);
            const float iA = 1.f / la, iB = 1.f / lb;
            const int cb = hh * 16 + 2 * qd;
            const int rA = mm * 16 + (lane >> 2), rB = rA + 8;
            if (rA < TT) {
                *(u32*)(sm + FU_QKV + rA * 400 + cb * 2)      = bfx2(o0[0] * iA, o0[1] * iA);
                *(u32*)(sm + FU_QKV + rA * 400 + cb * 2 + 16) = bfx2(o1[0] * iA, o1[1] * iA);
            }
            if (rB < TT) {
                *(u32*)(sm + FU_QKV + rB * 400 + cb * 2)      = bfx2(o0[2] * iB, o0[3] * iB);
                *(u32*)(sm + FU_QKV + rB * 400 + cb * 2 + 16) = bfx2(o1[2] * iB, o1[3] * iB);
            }
        }
    }
    __syncthreads();

    // ================= Phase 3: projection + residual + LN =================
    if (w < 13) {
        const u32 a_base = sb + FU_QKV +
            (u32)((w * 16 + (grp & 1) * 8 + (lane & 7)) * 400 + (grp >> 1) * 16);

        float acc[8][4];
        #pragma unroll
        for (int j = 0; j < 8; j++)
            #pragma unroll
            for (int q = 0; q < 4; q++) acc[j][q] = 0.f;

        #pragma unroll
        for (int ks = 0; ks < 4; ks++) {
            u32 Af[4];
            ldmx4(Af[0], Af[1], Af[2], Af[3], a_base + (u32)(ks * 32));
            #pragma unroll
            for (int jp = 0; jp < 4; jp++) {
                const u32* wf = g_wof + (jp * 4 + ks) * 128 + lane;
                u32 Bh[4];
                Bh[0] = wf[0];  Bh[1] = wf[32];
                Bh[2] = wf[64]; Bh[3] = wf[96];
                mma16816(acc[jp * 2],     Af, Bh[0], Bh[1]);
                mma16816(acc[jp * 2 + 1], Af, Bh[2], Bh[3]);
            }
        }

        const int rAl = w * 16 + (lane >> 2);
        const int rBl = rAl + 8;
        const bool okB = rBl < TT;
        const size_t rowA = rowg0 + rAl;
        const size_t rowB = rowg0 + rBl;
        const int cq = 2 * qd;

        #pragma unroll
        for (int j = 0; j < 8; j++) {
            const int c = 8 * j + cq;
            float2 xa = *(const float2*)(X + rowA * UU + c);
            acc[j][0] += xa.x; acc[j][1] += xa.y;
            if (okB) {
                float2 xb = *(const float2*)(X + rowB * UU + c);
                acc[j][2] += xb.x; acc[j][3] += xb.y;
            }
        }

        float sA = 0.f, sB = 0.f;
        #pragma unroll
        for (int j = 0; j < 8; j++) {
            sA += acc[j][0] + acc[j][1];
            sB += acc[j][2] + acc[j][3];
        }
        sA += __shfl_xor_sync(0xFFFFFFFFu, sA, 1);
        sA += __shfl_xor_sync(0xFFFFFFFFu, sA, 2);
        sB += __shfl_xor_sync(0xFFFFFFFFu, sB, 1);
        sB += __shfl_xor_sync(0xFFFFFFFFu, sB, 2);
        const float mA = sA * (1.0f / 64.0f);
        const float mB = sB * (1.0f / 64.0f);

        float vA = 0.f, vB = 0.f;
        #pragma unroll
        for (int j = 0; j < 8; j++) {
            float d0 = acc[j][0] - mA, d1 = acc[j][1] - mA;
            float d2 = acc[j][2] - mB, d3 = acc[j][3] - mB;
            vA = fmaf(d0, d0, fmaf(d1, d1, vA));
            vB = fmaf(d2, d2, fmaf(d3, d3, vB));
        }
        vA += __shfl_xor_sync(0xFFFFFFFFu, vA, 1);
        vA += __shfl_xor_sync(0xFFFFFFFFu, vA, 2);
        vB += __shfl_xor_sync(0xFFFFFFFFu, vB, 1);
        vB += __shfl_xor_sync(0xFFFFFFFFu, vB, 2);
        const float iA = rsqrtf(vA * (1.0f / 64.0f) + 1e-9f);
        const float iB = rsqrtf(vB * (1.0f / 64.0f) + 1e-9f);

        #pragma unroll
        for (int j = 0; j < 8; j++) {
            const int c = 8 * j + cq;
            const float2 gg = *(const float2*)(gamma + c);
            const float2 bb = *(const float2*)(beta + c);
            float2 oa;
            oa.x = fmaf((acc[j][0] - mA) * iA, gg.x, bb.x);
            oa.y = fmaf((acc[j][1] - mA) * iA, gg.y, bb.y);
            *(float2*)(out + rowA * UU + c) = oa;
            if (okB) {
                float2 ob;
                ob.x = fmaf((acc[j][2] - mB) * iB, gg.x, bb.x);
                ob.y = fmaf((acc[j][3] - mB) * iB, gg.y, bb.y);
                *(float2*)(out + rowB * UU + c) = ob;
            }
        }
    }
}

// ---------------------------------------------------------------------------
extern "C" void kernel_launch(void* const* d_in, const int* in_sizes, int n_in,
                              void* d_out, int out_size)
{
    const float* input_info = (const float*)d_in[0];
    const int*   keys_len   = (const int*)d_in[1];
    const float* W          = (const float*)d_in[2];
    const float* W_output   = (const float*)d_in[3];
    const float* gamma      = (const float*)d_in[4];
    const float* beta       = (const float*)d_in[5];
    float* out = (float*)d_out;

    cudaFuncSetAttribute(fused_mha, cudaFuncAttributeMaxDynamicSharedMemorySize, FU_SMEM);

    prep_weights<<<32, 256>>>(W, W_output);
    fused_mha<<<BB, 512, FU_SMEM>>>(input_info, keys_len, gamma, beta, out);
}

// round 17
// speedup vs baseline: 1.5572x; 1.0466x over previous
#include <cuda_runtime.h>
#include <math.h>

#define BB 1024
#define TT 200
#define EE 64
#define UU 64
#define HH 4
#define DH 16
#define C3U 192

typedef unsigned long long ull;
typedef unsigned int u32;
typedef unsigned short u16;

// Fragment-linearized weight tables, VECTOR layout:
// entry [frag f][lane l] = uint4 of the 4 regs -> offset (f*32 + l)*4 u32.
__device__ __align__(16) u32 g_wqf[6144];   // 48 frags (Q cols pre-scaled)
__device__ __align__(16) u32 g_wof[2048];   // 16 frags

// ---------------------------------------------------------------------------
__device__ __forceinline__ u16 f2bf(float f) {
    u32 u = __float_as_uint(f);
    u32 r = u + 0x7FFFu + ((u >> 16) & 1u);
    return (u16)(r >> 16);
}
__device__ __forceinline__ u32 bfx2(float lo, float hi) {
    u32 r; asm("cvt.rn.bf16x2.f32 %0, %1, %2;" : "=r"(r) : "f"(hi), "f"(lo));
    return r;
}
__device__ __forceinline__ float ex2f(float x) {   // MUFU.EX2
    float r; asm("ex2.approx.f32 %0, %1;" : "=f"(r) : "f"(x));
    return r;
}

// ---------------------------------------------------------------------------
__device__ __forceinline__ u32 smem_u32(const void* p) {
    u32 a; asm("{ .reg .u64 t; cvta.to.shared.u64 t, %1; cvt.u32.u64 %0, t; }"
               : "=r"(a) : "l"(p));
    return a;
}
__device__ __forceinline__ void ldmx4(u32& r0, u32& r1, u32& r2, u32& r3, u32 a) {
    asm volatile("ldmatrix.sync.aligned.m8n8.x4.shared.b16 {%0,%1,%2,%3}, [%4];"
                 : "=r"(r0), "=r"(r1), "=r"(r2), "=r"(r3) : "r"(a));
}
__device__ __forceinline__ void ldmx4t(u32& r0, u32& r1, u32& r2, u32& r3, u32 a) {
    asm volatile("ldmatrix.sync.aligned.m8n8.x4.trans.shared.b16 {%0,%1,%2,%3}, [%4];"
                 : "=r"(r0), "=r"(r1), "=r"(r2), "=r"(r3) : "r"(a));
}
__device__ __forceinline__ void mma16816(float* c, const u32* a, u32 b0, u32 b1) {
    asm volatile(
        "mma.sync.aligned.m16n8k16.row.col.f32.bf16.bf16.f32 "
        "{%0,%1,%2,%3}, {%4,%5,%6,%7}, {%8,%9}, {%0,%1,%2,%3};"
        : "+f"(c[0]), "+f"(c[1]), "+f"(c[2]), "+f"(c[3])
        : "r"(a[0]), "r"(a[1]), "r"(a[2]), "r"(a[3]), "r"(b0), "r"(b1));
}

// ---------------------------------------------------------------------------
// Kernel 0: fragment tables in vector layout (4 regs contiguous per lane).
// ---------------------------------------------------------------------------
__global__ void prep_weights(const float* __restrict__ W, const float* __restrict__ Wo)
{
    const float CSC = 0.36067376022224085f;
    const int i = blockIdx.x * 256 + threadIdx.x;   // 0..8191
    if (i < 6144) {          // W table
        const int iq   = i & 3;
        const int lane = (i >> 2) & 31;
        const int fu   = i >> 7;           // 0..47
        const int ks   = fu & 3;
        const int jpnc = fu >> 2;
        const int jp   = jpnc % 3;
        const int nc   = jpnc / 3;
        const int n = nc * 48 + jp * 16 + (iq >> 1) * 8 + (lane >> 2);
        const int k = ks * 16 + (iq & 1) * 8 + 2 * (lane & 3);
        const float sc = (n < UU) ? CSC : 1.0f;
        g_wqf[i] = (u32)f2bf(W[k * 192 + n] * sc) |
                   ((u32)f2bf(W[(k + 1) * 192 + n] * sc) << 16);
    } else if (i < 8192) {   // Wo table
        const int j = i - 6144;
        const int iq   = j & 3;
        const int lane = (j >> 2) & 31;
        const int fu   = j >> 7;           // 0..15
        const int ks   = fu & 3;
        const int jp   = fu >> 2;
        const int n = jp * 16 + (iq >> 1) * 8 + (lane >> 2);
        const int k = ks * 16 + (iq & 1) * 8 + 2 * (lane & 3);
        g_wof[j] = (u32)f2bf(Wo[k * 64 + n]) | ((u32)f2bf(Wo[(k + 1) * 64 + n]) << 16);
    }
}

// ---------------------------------------------------------------------------
// Fused kernel: one CTA per batch, 512 threads, 113.15KB smem -> 2 CTAs/SM.
// smem: [0,29952) X bf16 [208][72]; [29952,113152) QKV [208][200] stride 400
// ---------------------------------------------------------------------------
#define FU_X   0
#define FU_QKV 29952
#define FU_SMEM 113152

__global__ __launch_bounds__(512, 2)
void fused_mha(const float* __restrict__ X, const int* __restrict__ lens,
               const float* __restrict__ gamma, const float* __restrict__ beta,
               float* __restrict__ out)
{
    extern __shared__ char sm[];
    const u32 sb = smem_u32(sm);
    const int tid = threadIdx.x;
    const int b = blockIdx.x;
    const size_t rowg0 = (size_t)b * TT;

    // ---- stage X fp32 -> bf16 [208][72] ----
    {
        const float4* xs = (const float4*)(X + rowg0 * EE);
        for (int i = tid; i < 3200; i += 512) {
            float4 v = xs[i];
            const int r = i >> 4, q = i & 15;
            uint2 p;
            p.x = bfx2(v.x, v.y);
            p.y = bfx2(v.z, v.w);
            *(uint2*)(sm + FU_X + r * 144 + q * 8) = p;
        }
        if (tid < 72)
            *(uint4*)(sm + FU_X + 200 * 144 + tid * 16) = make_uint4(0, 0, 0, 0);
    }
    __syncthreads();

    const int lane = tid & 31;
    const int w    = tid >> 5;
    const int grp  = lane >> 3;
    const int qd   = lane & 3;

    int len = lens[b];
    if (len < 1) len = 1;
    if (len > TT) len = TT;
    const int kcnt = (len + 15) >> 4;

    // ================= Phase 1: QKV GEMM (52 tasks over 16 warps) ===========
    {
        const u32 a_off = (u32)(((grp & 1) * 8 + (lane & 7)) * 144 + (grp >> 1) * 16);

        for (int t = w; t < 52; t += 16) {
            const int mm = t % 13;
            const int nc = t / 13;
            if (nc >= 2 && mm >= kcnt) continue;

            const u32 a_base = sb + FU_X + (u32)(mm * 16) * 144 + a_off;
            float acc[6][4];
            #pragma unroll
            for (int j = 0; j < 6; j++)
                #pragma unroll
                for (int q = 0; q < 4; q++) acc[j][q] = 0.f;

            #pragma unroll
            for (int ks = 0; ks < 4; ks++) {
                u32 A[4];
                ldmx4(A[0], A[1], A[2], A[3], a_base + (u32)(ks * 32));
                #pragma unroll
                for (int jp = 0; jp < 3; jp++) {
                    const uint4 Bv = *(const uint4*)
                        (g_wqf + (((nc * 3 + jp) * 4 + ks) * 32 + lane) * 4);
                    mma16816(acc[jp * 2],     A, Bv.x, Bv.y);
                    mma16816(acc[jp * 2 + 1], A, Bv.z, Bv.w);
                }
            }
            const int rA = mm * 16 + (lane >> 2);
            const int rB = rA + 8;
            #pragma unroll
            for (int j = 0; j < 6; j++) {
                const int c = nc * 48 + 8 * j + 2 * qd;
                *(u32*)(sm + FU_QKV + rA * 400 + c * 2) = bfx2(acc[j][0], acc[j][1]);
                *(u32*)(sm + FU_QKV + rB * 400 + c * 2) = bfx2(acc[j][2], acc[j][3]);
            }
        }
    }
    __syncthreads();

    // ===== Phase 2: attention, 28 (head, mtile-pair) tasks, shared K/V =====
    {
        const u32 arow = (u32)(((grp & 1) * 8 + (lane & 7)) * 400 + (grp >> 1) * 16);
        const u32 krow = (u32)(((grp >> 1) * 8 + (lane & 7)) * 400 + (grp & 1) * 16);
        const u32 vrow = (u32)(((grp & 1) * 8 + (lane & 7)) * 400 + (grp >> 1) * 16);

        for (int t = w; t < 28; t += 16) {
            const int hh = t / 7;
            const int mp = t - hh * 7;
            const int mt0 = 2 * mp, mt1 = 2 * mp + 1;
            const bool do1 = (mt1 < 13);
            const u32 hb = (u32)(hh * 32);

            u32 A0[4], A1[4];
            const u32 a0 = sb + FU_QKV + (u32)(mt0 * 16) * 400 + hb + arow;
            ldmx4(A0[0], A0[1], A0[2], A0[3], a0);
            if (do1) {
                ldmx4(A1[0], A1[1], A1[2], A1[3], a0 + 6400);
            } else {
                A1[0] = A0[0]; A1[1] = A0[1]; A1[2] = A0[2]; A1[3] = A0[3];
            }
            const u32 ka = sb + FU_QKV + 128 + hb + krow;
            const u32 va = sb + FU_QKV + 256 + hb + vrow;

            float o00[4] = {0,0,0,0}, o01[4] = {0,0,0,0};
            float o10[4] = {0,0,0,0}, o11[4] = {0,0,0,0};
            float la0 = 0.f, lb0 = 0.f, la1 = 0.f, lb1 = 0.f;

            // ---- full (unmasked) chunks ----
            for (int np = 0; np < kcnt - 1; np++) {
                u32 KB[4], VB[4];
                ldmx4(KB[0], KB[1], KB[2], KB[3], ka + (u32)(np * 6400));
                ldmx4t(VB[0], VB[1], VB[2], VB[3], va + (u32)(np * 6400));

                u32 aE0[4], aE1[4];
                #pragma unroll
                for (int sub = 0; sub < 2; sub++) {
                    float s0[4] = {0.f, 0.f, 0.f, 0.f};
                    float s1[4] = {0.f, 0.f, 0.f, 0.f};
                    mma16816(s0, A0, KB[sub * 2], KB[sub * 2 + 1]);
                    mma16816(s1, A1, KB[sub * 2], KB[sub * 2 + 1]);
                    const float e0 = ex2f(s0[0]), e1 = ex2f(s0[1]);
                    const float e2 = ex2f(s0[2]), e3 = ex2f(s0[3]);
                    const float f0 = ex2f(s1[0]), f1 = ex2f(s1[1]);
                    const float f2 = ex2f(s1[2]), f3 = ex2f(s1[3]);
                    la0 += e0 + e1;  lb0 += e2 + e3;
                    la1 += f0 + f1;  lb1 += f2 + f3;
                    aE0[sub * 2]     = bfx2(e0, e1);
                    aE0[sub * 2 + 1] = bfx2(e2, e3);
                    aE1[sub * 2]     = bfx2(f0, f1);
                    aE1[sub * 2 + 1] = bfx2(f2, f3);
                }
                mma16816(o00, aE0, VB[0], VB[1]);
                mma16816(o01, aE0, VB[2], VB[3]);
                mma16816(o10, aE1, VB[0], VB[1]);
                mma16816(o11, aE1, VB[2], VB[3]);
            }
            // ---- final (masked) chunk ----
            {
                const int np = kcnt - 1;
                u32 KB[4], VB[4];
                ldmx4(KB[0], KB[1], KB[2], KB[3], ka + (u32)(np * 6400));
                ldmx4t(VB[0], VB[1], VB[2], VB[3], va + (u32)(np * 6400));

                const int c0 = np * 16 + 2 * qd;
                const float mk[4] = {
                    (c0     < len) ? 1.f : 0.f,
                    (c0 + 1 < len) ? 1.f : 0.f,
                    (c0 + 8 < len) ? 1.f : 0.f,
                    (c0 + 9 < len) ? 1.f : 0.f };

                u32 aE0[4], aE1[4];
                #pragma unroll
                for (int sub = 0; sub < 2; sub++) {
                    float s0[4] = {0.f, 0.f, 0.f, 0.f};
                    float s1[4] = {0.f, 0.f, 0.f, 0.f};
                    mma16816(s0, A0, KB[sub * 2], KB[sub * 2 + 1]);
                    mma16816(s1, A1, KB[sub * 2], KB[sub * 2 + 1]);
                    const float me = mk[sub * 2], mo = mk[sub * 2 + 1];
                    const float e0 = ex2f(s0[0]) * me, e1 = ex2f(s0[1]) * mo;
                    const float e2 = ex2f(s0[2]) * me, e3 = ex2f(s0[3]) * mo;
                    const float f0 = ex2f(s1[0]) * me, f1 = ex2f(s1[1]) * mo;
                    const float f2 = ex2f(s1[2]) * me, f3 = ex2f(s1[3]) * mo;
                    la0 += e0 + e1;  lb0 += e2 + e3;
                    la1 += f0 + f1;  lb1 += f2 + f3;
                    aE0[sub * 2]     = bfx2(e0, e1);
                    aE0[sub * 2 + 1] = bfx2(e2, e3);
                    aE1[sub * 2]     = bfx2(f0, f1);
                    aE1[sub * 2 + 1] = bfx2(f2, f3);
                }
                mma16816(o00, aE0, VB[0], VB[1]);
                mma16816(o01, aE0, VB[2], VB[3]);
                mma16816(o10, aE1, VB[0], VB[1]);
                mma16816(o11, aE1, VB[2], VB[3]);
            }

            // normalize + store over Q blocks
            const int cb = hh * 16 + 2 * qd;
            {
                float la = la0, lb = lb0;
                la += __shfl_xor_sync(0xFFFFFFFFu, la, 1);
                la += __shfl_xor_sync(0xFFFFFFFFu, la, 2);
                lb += __shfl_xor_sync(0xFFFFFFFFu, lb, 1);
                lb += __shfl_xor_sync(0xFFFFFFFFu, lb, 2);
                const float iA = 1.f / la, iB = 1.f / lb;
                const int rA = mt0 * 16 + (lane >> 2), rB = rA + 8;
                if (rA < TT) {
                    *(u32*)(sm + FU_QKV + rA * 400 + cb * 2)      = bfx2(o00[0] * iA, o00[1] * iA);
                    *(u32*)(sm + FU_QKV + rA * 400 + cb * 2 + 16) = bfx2(o01[0] * iA, o01[1] * iA);
                }
                if (rB < TT) {
                    *(u32*)(sm + FU_QKV + rB * 400 + cb * 2)      = bfx2(o00[2] * iB, o00[3] * iB);
                    *(u32*)(sm + FU_QKV + rB * 400 + cb * 2 + 16) = bfx2(o01[2] * iB, o01[3] * iB);
                }
            }
            if (do1) {
                float la = la1, lb = lb1;
                la += __shfl_xor_sync(0xFFFFFFFFu, la, 1);
                la += __shfl_xor_sync(0xFFFFFFFFu, la, 2);
                lb += __shfl_xor_sync(0xFFFFFFFFu, lb, 1);
                lb += __shfl_xor_sync(0xFFFFFFFFu, lb, 2);
                const float iA = 1.f / la, iB = 1.f / lb;
                const int rA = mt1 * 16 + (lane >> 2), rB = rA + 8;
                if (rA < TT) {
                    *(u32*)(sm + FU_QKV + rA * 400 + cb * 2)      = bfx2(o10[0] * iA, o10[1] * iA);
                    *(u32*)(sm + FU_QKV + rA * 400 + cb * 2 + 16) = bfx2(o11[0] * iA, o11[1] * iA);
                }
                if (rB < TT) {
                    *(u32*)(sm + FU_QKV + rB * 400 + cb * 2)      = bfx2(o10[2] * iB, o10[3] * iB);
                    *(u32*)(sm + FU_QKV + rB * 400 + cb * 2 + 16) = bfx2(o11[2] * iB, o11[3] * iB);
                }
            }
        }
    }
    __syncthreads();

    // ================= Phase 3: projection + residual + LN =================
    if (w < 13) {
        const u32 a_base = sb + FU_QKV +
            (u32)((w * 16 + (grp & 1) * 8 + (lane & 7)) * 400 + (grp >> 1) * 16);

        float acc[8][4];
        #pragma unroll
        for (int j = 0; j < 8; j++)
            #pragma unroll
            for (int q = 0; q < 4; q++) acc[j][q] = 0.f;

        #pragma unroll
        for (int ks = 0; ks < 4; ks++) {
            u32 Af[4];
            ldmx4(Af[0], Af[1], Af[2], Af[3], a_base + (u32)(ks * 32));
            #pragma unroll
            for (int jp = 0; jp < 4; jp++) {
                const uint4 Bv = *(const uint4*)
                    (g_wof + ((jp * 4 + ks) * 32 + lane) * 4);
                mma16816(acc[jp * 2],     Af, Bv.x, Bv.y);
                mma16816(acc[jp * 2 + 1], Af, Bv.z, Bv.w);
            }
        }

        const int rAl = w * 16 + (lane >> 2);
        const int rBl = rAl + 8;
        const bool okB = rBl < TT;
        const size_t rowA = rowg0 + rAl;
        const size_t rowB = rowg0 + rBl;
        const int cq = 2 * qd;

        #pragma unroll
        for (int j = 0; j < 8; j++) {
            const int c = 8 * j + cq;
            float2 xa = *(const float2*)(X + rowA * UU + c);
            acc[j][0] += xa.x; acc[j][1] += xa.y;
            if (okB) {
                float2 xb = *(const float2*)(X + rowB * UU + c);
                acc[j][2] += xb.x; acc[j][3] += xb.y;
            }
        }

        float sA = 0.f, sB = 0.f;
        #pragma unroll
        for (int j = 0; j < 8; j++) {
            sA += acc[j][0] + acc[j][1];
            sB += acc[j][2] + acc[j][3];
        }
        sA += __shfl_xor_sync(0xFFFFFFFFu, sA, 1);
        sA += __shfl_xor_sync(0xFFFFFFFFu, sA, 2);
        sB += __shfl_xor_sync(0xFFFFFFFFu, sB, 1);
        sB += __shfl_xor_sync(0xFFFFFFFFu, sB, 2);
        const float mA = sA * (1.0f / 64.0f);
        const float mB = sB * (1.0f / 64.0f);

        float vA = 0.f, vB = 0.f;
        #pragma unroll
        for (int j = 0; j < 8; j++) {
            float d0 = acc[j][0] - mA, d1 = acc[j][1] - mA;
            float d2 = acc[j][2] - mB, d3 = acc[j][3] - mB;
            vA = fmaf(d0, d0, fmaf(d1, d1, vA));
            vB = fmaf(d2, d2, fmaf(d3, d3, vB));
        }
        vA += __shfl_xor_sync(0xFFFFFFFFu, vA, 1);
        vA += __shfl_xor_sync(0xFFFFFFFFu, vA, 2);
        vB += __shfl_xor_sync(0xFFFFFFFFu, vB, 1);
        vB += __shfl_xor_sync(0xFFFFFFFFu, vB, 2);
        const float iA = rsqrtf(vA * (1.0f / 64.0f) + 1e-9f);
        const float iB = rsqrtf(vB * (1.0f / 64.0f) + 1e-9f);

        #pragma unroll
        for (int j = 0; j < 8; j++) {
            const int c = 8 * j + cq;
            const float2 gg = *(const float2*)(gamma + c);
            const float2 bb = *(const float2*)(beta + c);
            float2 oa;
            oa.x = fmaf((acc[j][0] - mA) * iA, gg.x, bb.x);
            oa.y = fmaf((acc[j][1] - mA) * iA, gg.y, bb.y);
            *(float2*)(out + rowA * UU + c) = oa;
            if (okB) {
                float2 ob;
                ob.x = fmaf((acc[j][2] - mB) * iB, gg.x, bb.x);
                ob.y = fmaf((acc[j][3] - mB) * iB, gg.y, bb.y);
                *(float2*)(out + rowB * UU + c) = ob;
            }
        }
    }
}

// ---------------------------------------------------------------------------
extern "C" void kernel_launch(void* const* d_in, const int* in_sizes, int n_in,
                              void* d_out, int out_size)
{
    const float* input_info = (const float*)d_in[0];
    const int*   keys_len   = (const int*)d_in[1];
    const float* W          = (const float*)d_in[2];
    const float* W_output   = (const float*)d_in[3];
    const float* gamma      = (const float*)d_in[4];
    const float* beta       = (const float*)d_in[5];
    float* out = (float*)d_out;

    cudaFuncSetAttribute(fused_mha, cudaFuncAttributeMaxDynamicSharedMemorySize, FU_SMEM);

    prep_weights<<<32, 256>>>(W, W_output);
    fused_mha<<<BB, 512, FU_SMEM>>>(input_info, keys_len, gamma, beta, out);
}